// round 9
// baseline (speedup 1.0000x reference)
#include <cuda_runtime.h>
#include <cstdint>

// Problem dims
#define BB 8
#define DD 1024
#define TT 8192
#define NCB 9
#define KK 1024
#define NT (BB*TT)        // 65536 tokens
#define CN (NCB*8)        // 72
#define NP (NT/2)         // 32768 token pairs

// Output layout (float32, tuple flattened in order)
#define OFF_CODES ((size_t)BB*DD*TT)                  // 67108864
#define OFF_LAT   (OFF_CODES + (size_t)BB*NCB*TT)     // 67698688
#define OFF_CL    (OFF_LAT + (size_t)BB*CN*TT)        // 72417280

#define THREADS 224
#define NBLK 152          // 152*224 = 34048 >= 32768 pairs

// Dynamic smem layout (float indices)
#define SM_CB2  0         // 8192 f : codebook pair-interleaved
#define SM_CC2  8192      // 1024 f
#define SM_WIND 9216      // u64[8192] : win dup'd            (16384 f)
#define SM_WO0D 25600     // u64[8192] : -wout0 dup'd         (16384 f)
#define SM_WO1  41984     // 8192 f    : -wout1 plain
#define SM_OB0D 50176     // u64[1024] : -ob0 dup'd           (2048 f)
#define SM_OB1D 52224     // u64[1024] : -ob1 dup'd           (2048 f)
#define SMEM_TOT (54272*4)   // 217088 bytes -> 1 block/SM

// Scratch (__device__ globals: allowed; no runtime allocation)
__device__ float g_resA[(size_t)BB*DD*TT];           // checkpoint buffer A (res1, res5)
__device__ float g_resB[(size_t)BB*DD*TT];           // checkpoint buffer B (res3, res7)
__device__ __align__(16) float g_WinT[NCB*DD*8];     // [n][d][c]
__device__ __align__(16) float g_WoutT[NCB*DD*8];    // [n][d][c]
__device__ __align__(16) float g_cbn[NCB*KK*8];      // normalized codebook (ref fp32 semantics)
__device__ __align__(16) float g_cc[NCB*KK];         // sum(c_n*c_n)
__device__ __align__(16) float g_lpart[NBLK];

// ---------------------------------------------------------------------------
// f32x2 packed helpers (each lane an exact IEEE fp32 op)
// ---------------------------------------------------------------------------
__device__ __forceinline__ unsigned long long pk2(float lo, float hi) {
    unsigned long long r;
    asm("mov.b64 %0, {%1, %2};" : "=l"(r) : "f"(lo), "f"(hi));
    return r;
}
__device__ __forceinline__ void upk2(unsigned long long v, float& lo, float& hi) {
    asm("mov.b64 {%0, %1}, %2;" : "=f"(lo), "=f"(hi) : "l"(v));
}
__device__ __forceinline__ unsigned long long ffma2(unsigned long long a, unsigned long long b, unsigned long long c) {
    unsigned long long r;
    asm("fma.rn.f32x2 %0, %1, %2, %3;" : "=l"(r) : "l"(a), "l"(b), "l"(c));
    return r;
}
__device__ __forceinline__ unsigned long long fmul2(unsigned long long a, unsigned long long b) {
    unsigned long long r;
    asm("mul.rn.f32x2 %0, %1, %2;" : "=l"(r) : "l"(a), "l"(b));
    return r;
}
__device__ __forceinline__ unsigned long long fadd2(unsigned long long a, unsigned long long b) {
    unsigned long long r;
    asm("add.rn.f32x2 %0, %1, %2;" : "=l"(r) : "l"(a), "l"(b));
    return r;
}

// ---------------------------------------------------------------------------
// Prep: weight-norm input rows (fp64 norms), store [n][d][8c]
// ---------------------------------------------------------------------------
__global__ void kp_win(const float* __restrict__ in_v, const float* __restrict__ in_g) {
    const int row = blockIdx.x;               // 0..71 = n*8 + c
    const int n = row >> 3, c = row & 7;
    const float* src = in_v + (size_t)row * DD;
    __shared__ double red[256];
    double ss = 0.0;
    for (int d = threadIdx.x; d < DD; d += 256) { double v = src[d]; ss += v*v; }
    red[threadIdx.x] = ss; __syncthreads();
    for (int s = 128; s > 0; s >>= 1) {
        if (threadIdx.x < s) red[threadIdx.x] += red[threadIdx.x + s];
        __syncthreads();
    }
    const float scale = (float)((double)in_g[row] / sqrt(red[0]));
    for (int d = threadIdx.x; d < DD; d += 256)
        g_WinT[(size_t)n*DD*8 + d*8 + c] = src[d] * scale;
}

// ---------------------------------------------------------------------------
// Prep: weight-norm output rows (norm over C=8, fp64), store [n][d][8c]
// ---------------------------------------------------------------------------
__global__ void kp_wout(const float* __restrict__ out_v, const float* __restrict__ out_g) {
    const int i = blockIdx.x * 256 + threadIdx.x;   // (n, d)
    if (i >= NCB*DD) return;
    const int n = i / DD, d = i - n*DD;
    const float* v = out_v + (size_t)i * 8;
    double ss = 0.0;
    #pragma unroll
    for (int c = 0; c < 8; c++) { double x = v[c]; ss += x*x; }
    const float sc = (float)((double)out_g[i] / sqrt(ss));
    #pragma unroll
    for (int c = 0; c < 8; c++) g_WoutT[(size_t)n*DD*8 + d*8 + c] = v[c] * sc;
}

// ---------------------------------------------------------------------------
// Prep: normalized codebook + cc = sum(c_n^2), replicating fp32 elementwise ops
// ---------------------------------------------------------------------------
__global__ void kp_cb(const float* __restrict__ cb) {
    const int r = blockIdx.x * 256 + threadIdx.x;   // (n, k)
    if (r >= NCB*KK) return;
    const float* v = cb + (size_t)r * 8;
    float ss = 0.f;
    #pragma unroll
    for (int c = 0; c < 8; c++) ss = __fadd_rn(ss, __fmul_rn(v[c], v[c]));
    const float nr = fmaxf(__fsqrt_rn(ss), 1e-12f);
    float cn[8];
    #pragma unroll
    for (int c = 0; c < 8; c++) cn[c] = __fdiv_rn(v[c], nr);
    #pragma unroll
    for (int c = 0; c < 8; c++) g_cbn[(size_t)r*8 + c] = cn[c];
    float s2 = 0.f;
    #pragma unroll
    for (int c = 0; c < 8; c++) s2 = __fadd_rn(s2, __fmul_rn(cn[c], cn[c]));
    g_cc[r] = s2;
}

// ---------------------------------------------------------------------------
// Mega kernel: one thread owns TWO adjacent tokens (2p, 2p+1) through all 9
// stages + final pass. f32x2 lanes = tokens; per-lane op sequences are
// bit-identical to the R6/R8 passing kernels. Tables pre-duplicated in smem;
// wout/ob stored NEGATED (exact under IEEE sign symmetry) so the residual
// update is pure ffma2 chains + fadd2.
// ---------------------------------------------------------------------------
__global__ void __launch_bounds__(THREADS) k_mega(const float* __restrict__ z,
                                                  const float* __restrict__ in_b,
                                                  const float* __restrict__ out_b,
                                                  const float* __restrict__ cb_raw,
                                                  float* __restrict__ out) {
    extern __shared__ float smf[];
    __shared__ float red[256];

    const int tid = threadIdx.x;
    int p = blockIdx.x * THREADS + tid;
    const int active = (p < NP) ? 1 : 0;
    if (!active) p = NP - 1;      // clones duplicate last pair (identical writes)
    const int token = 2 * p;
    const int b = token >> 13;
    const int t = token & (TT - 1);
    const size_t off = (size_t)b*DD*TT + t;

    unsigned long long* wind = (unsigned long long*)&smf[SM_WIND];
    unsigned long long* wo0d = (unsigned long long*)&smf[SM_WO0D];
    unsigned long long* ob0d = (unsigned long long*)&smf[SM_OB0D];
    unsigned long long* ob1d = (unsigned long long*)&smf[SM_OB1D];

    float zqA0[8] = {0,0,0,0,0,0,0,0}, zqA1[8] = {0,0,0,0,0,0,0,0};
    float zqB0[8] = {0,0,0,0,0,0,0,0}, zqB1[8] = {0,0,0,0,0,0,0,0};
    float lacc = 0.f;

    for (int n = 0; n < NCB; n++) {
        const int nproj = (n == 0) ? 0 : (((n & 1) && n >= 3) ? 2 : 1);
        const int m0 = n - nproj;
        const float* rin = (n <= 1) ? z
                          : ((n == 2 || n == 3 || n == 6 || n == 7) ? (const float*)g_resA
                                                                    : (const float*)g_resB);
        float* wr = nullptr;
        if (n == 1) wr = g_resA;
        else if (n == 3) wr = g_resB;
        else if (n == 5) wr = g_resA;
        else if (n == 7) wr = g_resB;

        __syncthreads();   // previous stage done with smem
        for (int i = tid; i < KK*8; i += THREADS) {
            const int k = i >> 3, c = i & 7;
            smf[SM_CB2 + (k >> 1)*16 + c*2 + (k & 1)] = g_cbn[(size_t)n*KK*8 + i];
        }
        for (int k = tid; k < KK; k += THREADS) smf[SM_CC2 + k] = g_cc[n*KK + k];
        for (int i = tid; i < DD*8; i += THREADS) {
            const float v = g_WinT[(size_t)n*DD*8 + i];
            wind[i] = pk2(v, v);
        }
        if (nproj >= 1) {
            for (int i = tid; i < DD*8; i += THREADS) {
                const float v = -g_WoutT[(size_t)m0*DD*8 + i];
                wo0d[i] = pk2(v, v);
            }
            for (int i = tid; i < DD; i += THREADS) {
                const float v = -out_b[m0*DD + i];
                ob0d[i] = pk2(v, v);
            }
        }
        if (nproj == 2) {
            for (int i = tid; i < DD*8; i += THREADS)
                smf[SM_WO1 + i] = -g_WoutT[(size_t)(m0 + 1)*DD*8 + i];
            for (int i = tid; i < DD; i += THREADS) {
                const float v = -out_b[(m0 + 1)*DD + i];
                ob1d[i] = pk2(v, v);
            }
        }
        __syncthreads();

        unsigned long long zp2[8], za2[8];
        #pragma unroll
        for (int c = 0; c < 8; c++) {
            zp2[c] = (nproj == 2) ? pk2(zqB0[c], zqB1[c]) : pk2(zqA0[c], zqA1[c]);
            za2[c] = pk2(zqA0[c], zqA1[c]);
        }

        // ---- Phase 1: stream residual pair, apply projections, accumulate z_e ----
        unsigned long long acc[8] = {0,0,0,0,0,0,0,0};
        unsigned long long rbuf[8];
        #pragma unroll
        for (int i = 0; i < 8; i++)
            rbuf[i] = *(const unsigned long long*)(rin + off + (size_t)i*TT);

        for (int d0 = 0; d0 < DD; d0 += 8) {
            unsigned long long rnx[8];
            const bool more = (d0 + 8) < DD;
            if (more) {
                #pragma unroll
                for (int i = 0; i < 8; i++)
                    rnx[i] = *(const unsigned long long*)(rin + off + (size_t)(d0 + 8 + i)*TT);
            }
            #pragma unroll
            for (int i = 0; i < 8; i++) {
                const int d = d0 + i;
                unsigned long long r2 = rbuf[i];
                if (nproj >= 1) {
                    const ulonglong2* w = (const ulonglong2*)(wo0d + d*8);
                    const ulonglong2 q0 = w[0], q1 = w[1], q2 = w[2], q3 = w[3];
                    unsigned long long dt = ffma2(q0.x, zp2[0], 0ull);
                    dt = ffma2(q0.y, zp2[1], dt);
                    dt = ffma2(q1.x, zp2[2], dt);
                    dt = ffma2(q1.y, zp2[3], dt);
                    dt = ffma2(q2.x, zp2[4], dt);
                    dt = ffma2(q2.y, zp2[5], dt);
                    dt = ffma2(q3.x, zp2[6], dt);
                    dt = ffma2(q3.y, zp2[7], dt);
                    dt = fadd2(dt, ob0d[d]);    // = -(dot + ob) exactly
                    r2 = fadd2(r2, dt);         // = rn(r - pr) exactly
                }
                if (nproj == 2) {
                    const float4 wa = *(const float4*)&smf[SM_WO1 + d*8];
                    const float4 wb = *(const float4*)&smf[SM_WO1 + d*8 + 4];
                    unsigned long long dt = ffma2(pk2(wa.x, wa.x), za2[0], 0ull);
                    dt = ffma2(pk2(wa.y, wa.y), za2[1], dt);
                    dt = ffma2(pk2(wa.z, wa.z), za2[2], dt);
                    dt = ffma2(pk2(wa.w, wa.w), za2[3], dt);
                    dt = ffma2(pk2(wb.x, wb.x), za2[4], dt);
                    dt = ffma2(pk2(wb.y, wb.y), za2[5], dt);
                    dt = ffma2(pk2(wb.z, wb.z), za2[6], dt);
                    dt = ffma2(pk2(wb.w, wb.w), za2[7], dt);
                    dt = fadd2(dt, ob1d[d]);
                    r2 = fadd2(r2, dt);
                }
                if (wr) *(unsigned long long*)(wr + off + (size_t)d*TT) = r2;
                const ulonglong2* wi = (const ulonglong2*)(wind + d*8);
                const ulonglong2 a0 = wi[0], a1 = wi[1], a2 = wi[2], a3 = wi[3];
                acc[0] = ffma2(a0.x, r2, acc[0]);
                acc[1] = ffma2(a0.y, r2, acc[1]);
                acc[2] = ffma2(a1.x, r2, acc[2]);
                acc[3] = ffma2(a1.y, r2, acc[3]);
                acc[4] = ffma2(a2.x, r2, acc[4]);
                acc[5] = ffma2(a2.y, r2, acc[5]);
                acc[6] = ffma2(a3.x, r2, acc[6]);
                acc[7] = ffma2(a3.y, r2, acc[7]);
            }
            if (more) {
                #pragma unroll
                for (int i = 0; i < 8; i++) rbuf[i] = rnx[i];
            }
        }

        // ---- Phase 2: z_e per token, normalize (identical scalar ops) ----
        float e0[8], e1[8];
        #pragma unroll
        for (int c = 0; c < 8; c++) {
            upk2(acc[c], e0[c], e1[c]);
            const float vb = __ldg(in_b + n*8 + c);
            e0[c] = __fadd_rn(e0[c], vb);
            e1[c] = __fadd_rn(e1[c], vb);
        }

        unsigned long long enA[8], enB[8], eepA, eepB;
        {
            float ssq = 0.f;
            #pragma unroll
            for (int c = 0; c < 8; c++) ssq = __fadd_rn(ssq, __fmul_rn(e0[c], e0[c]));
            const float rho = fmaxf(__fsqrt_rn(ssq), 1e-12f);
            float en[8], ee = 0.f;
            #pragma unroll
            for (int c = 0; c < 8; c++) en[c] = __fdiv_rn(e0[c], rho);
            #pragma unroll
            for (int c = 0; c < 8; c++) ee = __fadd_rn(ee, __fmul_rn(en[c], en[c]));
            #pragma unroll
            for (int c = 0; c < 8; c++) enA[c] = pk2(en[c], en[c]);
            eepA = pk2(ee, ee);
        }
        {
            float ssq = 0.f;
            #pragma unroll
            for (int c = 0; c < 8; c++) ssq = __fadd_rn(ssq, __fmul_rn(e1[c], e1[c]));
            const float rho = fmaxf(__fsqrt_rn(ssq), 1e-12f);
            float en[8], ee = 0.f;
            #pragma unroll
            for (int c = 0; c < 8; c++) en[c] = __fdiv_rn(e1[c], rho);
            #pragma unroll
            for (int c = 0; c < 8; c++) ee = __fadd_rn(ee, __fmul_rn(en[c], en[c]));
            #pragma unroll
            for (int c = 0; c < 8; c++) enB[c] = pk2(en[c], en[c]);
            eepB = pk2(ee, ee);
        }
        const unsigned long long m2 = pk2(-2.f, -2.f);

        // ---- argmin: both tokens share the codebook LDS; per-token math and
        //      4-chain first-wins merge identical to R8 ----
        float aA = 3.4e38f, aB = 3.4e38f, aC = 3.4e38f, aD = 3.4e38f;
        int   jA = 0, jB = 0, jC = 0, jD = 0;
        float bA_ = 3.4e38f, bB_ = 3.4e38f, bC_ = 3.4e38f, bD_ = 3.4e38f;
        int   kA = 0, kB = 0, kC = 0, kD = 0;
        const unsigned long long* cbu = (const unsigned long long*)&smf[SM_CB2];
        const unsigned long long* ccu = (const unsigned long long*)&smf[SM_CC2];
        for (int k2 = 0; k2 < KK/2; k2 += 2) {
            const ulonglong2 ca0 = *(const ulonglong2*)(cbu + k2*8);
            const ulonglong2 cb0 = *(const ulonglong2*)(cbu + k2*8 + 2);
            const ulonglong2 cc0 = *(const ulonglong2*)(cbu + k2*8 + 4);
            const ulonglong2 cd0 = *(const ulonglong2*)(cbu + k2*8 + 6);
            const ulonglong2 ca1 = *(const ulonglong2*)(cbu + (k2+1)*8);
            const ulonglong2 cb1 = *(const ulonglong2*)(cbu + (k2+1)*8 + 2);
            const ulonglong2 cc1 = *(const ulonglong2*)(cbu + (k2+1)*8 + 4);
            const ulonglong2 cd1 = *(const ulonglong2*)(cbu + (k2+1)*8 + 6);
            const unsigned long long ccv0 = ccu[k2], ccv1 = ccu[k2+1];
            // token A
            {
                unsigned long long dp0 = fmul2(enA[0], ca0.x);
                unsigned long long dp1 = fmul2(enA[0], ca1.x);
                dp0 = ffma2(enA[1], ca0.y, dp0);  dp1 = ffma2(enA[1], ca1.y, dp1);
                dp0 = ffma2(enA[2], cb0.x, dp0);  dp1 = ffma2(enA[2], cb1.x, dp1);
                dp0 = ffma2(enA[3], cb0.y, dp0);  dp1 = ffma2(enA[3], cb1.y, dp1);
                dp0 = ffma2(enA[4], cc0.x, dp0);  dp1 = ffma2(enA[4], cc1.x, dp1);
                dp0 = ffma2(enA[5], cc0.y, dp0);  dp1 = ffma2(enA[5], cc1.y, dp1);
                dp0 = ffma2(enA[6], cd0.x, dp0);  dp1 = ffma2(enA[6], cd1.x, dp1);
                dp0 = ffma2(enA[7], cd0.y, dp0);  dp1 = ffma2(enA[7], cd1.y, dp1);
                const unsigned long long t0 = ffma2(m2, dp0, eepA);
                const unsigned long long t1 = ffma2(m2, dp1, eepA);
                const unsigned long long di0 = fadd2(t0, ccv0);
                const unsigned long long di1 = fadd2(t1, ccv1);
                float d0v, d1v, d2v, d3v;
                upk2(di0, d0v, d1v); upk2(di1, d2v, d3v);
                if (d0v < aA) { aA = d0v; jA = 2*k2; }
                if (d1v < aB) { aB = d1v; jB = 2*k2 + 1; }
                if (d2v < aC) { aC = d2v; jC = 2*k2 + 2; }
                if (d3v < aD) { aD = d3v; jD = 2*k2 + 3; }
            }
            // token B
            {
                unsigned long long dp0 = fmul2(enB[0], ca0.x);
                unsigned long long dp1 = fmul2(enB[0], ca1.x);
                dp0 = ffma2(enB[1], ca0.y, dp0);  dp1 = ffma2(enB[1], ca1.y, dp1);
                dp0 = ffma2(enB[2], cb0.x, dp0);  dp1 = ffma2(enB[2], cb1.x, dp1);
                dp0 = ffma2(enB[3], cb0.y, dp0);  dp1 = ffma2(enB[3], cb1.y, dp1);
                dp0 = ffma2(enB[4], cc0.x, dp0);  dp1 = ffma2(enB[4], cc1.x, dp1);
                dp0 = ffma2(enB[5], cc0.y, dp0);  dp1 = ffma2(enB[5], cc1.y, dp1);
                dp0 = ffma2(enB[6], cd0.x, dp0);  dp1 = ffma2(enB[6], cd1.x, dp1);
                dp0 = ffma2(enB[7], cd0.y, dp0);  dp1 = ffma2(enB[7], cd1.y, dp1);
                const unsigned long long t0 = ffma2(m2, dp0, eepB);
                const unsigned long long t1 = ffma2(m2, dp1, eepB);
                const unsigned long long di0 = fadd2(t0, ccv0);
                const unsigned long long di1 = fadd2(t1, ccv1);
                float d0v, d1v, d2v, d3v;
                upk2(di0, d0v, d1v); upk2(di1, d2v, d3v);
                if (d0v < bA_) { bA_ = d0v; kA = 2*k2; }
                if (d1v < bB_) { bB_ = d1v; kB = 2*k2 + 1; }
                if (d2v < bC_) { bC_ = d2v; kC = 2*k2 + 2; }
                if (d3v < bD_) { bD_ = d3v; kD = 2*k2 + 3; }
            }
        }
        float best0 = aA; int bi0 = jA;
        if (aB < best0 || (aB == best0 && jB < bi0)) { best0 = aB; bi0 = jB; }
        if (aC < best0 || (aC == best0 && jC < bi0)) { best0 = aC; bi0 = jC; }
        if (aD < best0 || (aD == best0 && jD < bi0)) { best0 = aD; bi0 = jD; }
        float best1 = bA_; int bi1 = kA;
        if (bB_ < best1 || (bB_ == best1 && kB < bi1)) { best1 = bB_; bi1 = kB; }
        if (bC_ < best1 || (bC_ == best1 && kC < bi1)) { best1 = bC_; bi1 = kC; }
        if (bD_ < best1 || (bD_ == best1 && kD < bi1)) { best1 = bD_; bi1 = kD; }

        // ---- Phase 3: winners, straight-through, outputs ----
        const float* q0p = cb_raw + ((size_t)n*KK + bi0)*8;
        const float* q1p = cb_raw + ((size_t)n*KK + bi1)*8;
        const float4 qa0 = __ldg((const float4*)q0p);
        const float4 qa1 = __ldg((const float4*)(q0p + 4));
        const float4 qb0 = __ldg((const float4*)q1p);
        const float4 qb1 = __ldg((const float4*)(q1p + 4));
        const float q0[8] = {qa0.x, qa0.y, qa0.z, qa0.w, qa1.x, qa1.y, qa1.z, qa1.w};
        const float q1[8] = {qb0.x, qb0.y, qb0.z, qb0.w, qb1.x, qb1.y, qb1.z, qb1.w};

        #pragma unroll
        for (int c = 0; c < 8; c++) {
            const float dl0 = __fsub_rn(e0[c], q0[c]);
            lacc = fmaf(dl0, dl0, lacc);
            const float dl1 = __fsub_rn(e1[c], q1[c]);
            lacc = fmaf(dl1, dl1, lacc);
            zqB0[c] = zqA0[c]; zqB1[c] = zqA1[c];
            zqA0[c] = __fadd_rn(e0[c], __fsub_rn(q0[c], e0[c]));
            zqA1[c] = __fadd_rn(e1[c], __fsub_rn(q1[c], e1[c]));
        }

        *(float2*)&out[OFF_CODES + (size_t)b*NCB*TT + (size_t)n*TT + t] =
            make_float2((float)bi0, (float)bi1);
        #pragma unroll
        for (int c = 0; c < 8; c++)
            *(float2*)&out[OFF_LAT + (size_t)b*CN*TT + (size_t)(n*8 + c)*TT + t] =
                make_float2(e0[c], e1[c]);
    }

    // ---- Final pass: res7(B) -> fly proj7 (zqB) -> proj8 (zqA) -> out = z - res9 ----
    __syncthreads();
    for (int i = tid; i < DD*8; i += THREADS) {
        const float v7 = -g_WoutT[(size_t)7*DD*8 + i];
        wo0d[i] = pk2(v7, v7);
        const float v8 = -g_WoutT[(size_t)8*DD*8 + i];
        wind[i] = pk2(v8, v8);
    }
    for (int i = tid; i < DD; i += THREADS) {
        const float v7 = -out_b[7*DD + i];
        ob0d[i] = pk2(v7, v7);
        const float v8 = -out_b[8*DD + i];
        ob1d[i] = pk2(v8, v8);
    }
    __syncthreads();

    {
        unsigned long long zb2[8], za2[8];
        #pragma unroll
        for (int c = 0; c < 8; c++) {
            zb2[c] = pk2(zqB0[c], zqB1[c]);
            za2[c] = pk2(zqA0[c], zqA1[c]);
        }
        const unsigned long long SGN = 0x8000000080000000ull;
        unsigned long long rb[8], zb[8];
        #pragma unroll
        for (int i = 0; i < 8; i++) {
            rb[i] = *(const unsigned long long*)((const float*)g_resB + off + (size_t)i*TT);
            zb[i] = *(const unsigned long long*)(z + off + (size_t)i*TT);
        }
        for (int d0 = 0; d0 < DD; d0 += 8) {
            unsigned long long rn_[8], zn_[8];
            const bool more = (d0 + 8) < DD;
            if (more) {
                #pragma unroll
                for (int i = 0; i < 8; i++) {
                    rn_[i] = *(const unsigned long long*)((const float*)g_resB + off + (size_t)(d0 + 8 + i)*TT);
                    zn_[i] = *(const unsigned long long*)(z + off + (size_t)(d0 + 8 + i)*TT);
                }
            }
            #pragma unroll
            for (int i = 0; i < 8; i++) {
                const int d = d0 + i;
                unsigned long long r2 = rb[i];
                {   // proj7 with zqB
                    const ulonglong2* w = (const ulonglong2*)(wo0d + d*8);
                    const ulonglong2 p0 = w[0], p1 = w[1], p2 = w[2], p3 = w[3];
                    unsigned long long dt = ffma2(p0.x, zb2[0], 0ull);
                    dt = ffma2(p0.y, zb2[1], dt);
                    dt = ffma2(p1.x, zb2[2], dt);
                    dt = ffma2(p1.y, zb2[3], dt);
                    dt = ffma2(p2.x, zb2[4], dt);
                    dt = ffma2(p2.y, zb2[5], dt);
                    dt = ffma2(p3.x, zb2[6], dt);
                    dt = ffma2(p3.y, zb2[7], dt);
                    dt = fadd2(dt, ob0d[d]);
                    r2 = fadd2(r2, dt);
                }
                {   // proj8 with zqA
                    const ulonglong2* w = (const ulonglong2*)(wind + d*8);
                    const ulonglong2 p0 = w[0], p1 = w[1], p2 = w[2], p3 = w[3];
                    unsigned long long dt = ffma2(p0.x, za2[0], 0ull);
                    dt = ffma2(p0.y, za2[1], dt);
                    dt = ffma2(p1.x, za2[2], dt);
                    dt = ffma2(p1.y, za2[3], dt);
                    dt = ffma2(p2.x, za2[4], dt);
                    dt = ffma2(p2.y, za2[5], dt);
                    dt = ffma2(p3.x, za2[6], dt);
                    dt = ffma2(p3.y, za2[7], dt);
                    dt = fadd2(dt, ob1d[d]);
                    r2 = fadd2(r2, dt);
                }
                // out = rn(z - r9) == fadd2(z, -r9) exactly
                *(unsigned long long*)&out[off + (size_t)d*TT] = fadd2(zb[i], r2 ^ SGN);
            }
            if (more) {
                #pragma unroll
                for (int i = 0; i < 8; i++) { rb[i] = rn_[i]; zb[i] = zn_[i]; }
            }
        }
    }

    // ---- loss partial (clones contribute 0) ----
    red[tid] = active ? lacc : 0.f;
    if (tid < 256 - THREADS) red[THREADS + tid] = 0.f;
    __syncthreads();
    for (int s = 128; s > 0; s >>= 1) {
        if (tid < s) red[tid] += red[tid + s];
        __syncthreads();
    }
    if (tid == 0) g_lpart[blockIdx.x] = red[0];
}

// ---------------------------------------------------------------------------
// Deterministic loss reduce in fp64: cl == cbl (identical forward values)
// ---------------------------------------------------------------------------
__global__ void k_loss(float* __restrict__ out) {
    if (threadIdx.x != 0 || blockIdx.x != 0) return;
    double s = 0.0;
    for (int i = 0; i < NBLK; i++) s += (double)g_lpart[i];
    const float v = (float)(s / 524288.0);   // per-stage mean over B*C*T, summed
    out[OFF_CL]     = v;
    out[OFF_CL + 1] = v;
}

// ---------------------------------------------------------------------------
extern "C" void kernel_launch(void* const* d_in, const int* in_sizes, int n_in,
                              void* d_out, int out_size) {
    (void)in_sizes; (void)n_in; (void)out_size;
    const float* z     = (const float*)d_in[0];
    const float* in_v  = (const float*)d_in[1];
    const float* in_g  = (const float*)d_in[2];
    const float* in_b  = (const float*)d_in[3];
    const float* out_v = (const float*)d_in[4];
    const float* out_g = (const float*)d_in[5];
    const float* out_b = (const float*)d_in[6];
    const float* cb    = (const float*)d_in[7];
    float* out = (float*)d_out;

    cudaFuncSetAttribute(k_mega, cudaFuncAttributeMaxDynamicSharedMemorySize, SMEM_TOT);

    kp_win  <<<72, 256>>>(in_v, in_g);
    kp_wout <<<(NCB*DD + 255)/256, 256>>>(out_v, out_g);
    kp_cb   <<<(NCB*KK + 255)/256, 256>>>(cb);

    k_mega <<<NBLK, THREADS, SMEM_TOT>>>(z, in_b, out_b, cb, out);
    k_loss <<<1, 32>>>(out);
}

// round 10
// speedup vs baseline: 1.1511x; 1.1511x over previous
#include <cuda_runtime.h>
#include <cstdint>

// Problem dims
#define BB 8
#define DD 1024
#define TT 8192
#define NCB 9
#define KK 1024
#define NT (BB*TT)        // 65536 tokens
#define CN (NCB*8)        // 72
#define NP (NT/2)         // 32768 token pairs

// Output layout (float32, tuple flattened in order)
#define OFF_CODES ((size_t)BB*DD*TT)                  // 67108864
#define OFF_LAT   (OFF_CODES + (size_t)BB*NCB*TT)     // 67698688
#define OFF_CL    (OFF_LAT + (size_t)BB*CN*TT)        // 72417280

#define THREADS 224
#define NBLK 152          // 152*224 = 34048 >= 32768 pairs

// Dynamic smem layout (float indices)
#define SM_CB2  0         // 8192 f : codebook pair-interleaved
#define SM_CC2  8192      // 1024 f
#define SM_WIND 9216      // u64[8192] : win dup'd            (16384 f)
#define SM_WO0D 25600     // u64[8192] : -wout0 dup'd         (16384 f)
#define SM_WO1  41984     // 8192 f    : -wout1 plain
#define SM_OB0D 50176     // u64[1024] : -ob0 dup'd           (2048 f)
#define SM_OB1D 52224     // u64[1024] : -ob1 dup'd           (2048 f)
#define SMEM_TOT (54272*4)   // 217088 bytes -> 1 block/SM

// Scratch (__device__ globals: allowed; no runtime allocation)
__device__ float g_resA[(size_t)BB*DD*TT];           // checkpoint buffer A (res1, res5)
__device__ float g_resB[(size_t)BB*DD*TT];           // checkpoint buffer B (res3, res7)
__device__ __align__(16) float g_WinT[NCB*DD*8];     // [n][d][c]
__device__ __align__(16) float g_WoutT[NCB*DD*8];    // [n][d][c]
__device__ __align__(16) float g_cbn[NCB*KK*8];      // normalized codebook (ref fp32 semantics)
__device__ __align__(16) float g_cc[NCB*KK];         // sum(c_n*c_n)
__device__ __align__(16) float g_lpart[NBLK];

// ---------------------------------------------------------------------------
// f32x2 packed helpers (each lane an exact IEEE fp32 op)
// ---------------------------------------------------------------------------
__device__ __forceinline__ unsigned long long pk2(float lo, float hi) {
    unsigned long long r;
    asm("mov.b64 %0, {%1, %2};" : "=l"(r) : "f"(lo), "f"(hi));
    return r;
}
__device__ __forceinline__ void upk2(unsigned long long v, float& lo, float& hi) {
    asm("mov.b64 {%0, %1}, %2;" : "=f"(lo), "=f"(hi) : "l"(v));
}
__device__ __forceinline__ unsigned long long ffma2(unsigned long long a, unsigned long long b, unsigned long long c) {
    unsigned long long r;
    asm("fma.rn.f32x2 %0, %1, %2, %3;" : "=l"(r) : "l"(a), "l"(b), "l"(c));
    return r;
}
__device__ __forceinline__ unsigned long long fmul2(unsigned long long a, unsigned long long b) {
    unsigned long long r;
    asm("mul.rn.f32x2 %0, %1, %2;" : "=l"(r) : "l"(a), "l"(b));
    return r;
}
__device__ __forceinline__ unsigned long long fadd2(unsigned long long a, unsigned long long b) {
    unsigned long long r;
    asm("add.rn.f32x2 %0, %1, %2;" : "=l"(r) : "l"(a), "l"(b));
    return r;
}

// ---------------------------------------------------------------------------
// Prep: weight-norm input rows (fp64 norms), store [n][d][8c]
// ---------------------------------------------------------------------------
__global__ void kp_win(const float* __restrict__ in_v, const float* __restrict__ in_g) {
    const int row = blockIdx.x;               // 0..71 = n*8 + c
    const int n = row >> 3, c = row & 7;
    const float* src = in_v + (size_t)row * DD;
    __shared__ double red[256];
    double ss = 0.0;
    for (int d = threadIdx.x; d < DD; d += 256) { double v = src[d]; ss += v*v; }
    red[threadIdx.x] = ss; __syncthreads();
    for (int s = 128; s > 0; s >>= 1) {
        if (threadIdx.x < s) red[threadIdx.x] += red[threadIdx.x + s];
        __syncthreads();
    }
    const float scale = (float)((double)in_g[row] / sqrt(red[0]));
    for (int d = threadIdx.x; d < DD; d += 256)
        g_WinT[(size_t)n*DD*8 + d*8 + c] = src[d] * scale;
}

// ---------------------------------------------------------------------------
// Prep: weight-norm output rows (norm over C=8, fp64), store [n][d][8c]
// ---------------------------------------------------------------------------
__global__ void kp_wout(const float* __restrict__ out_v, const float* __restrict__ out_g) {
    const int i = blockIdx.x * 256 + threadIdx.x;   // (n, d)
    if (i >= NCB*DD) return;
    const int n = i / DD, d = i - n*DD;
    const float* v = out_v + (size_t)i * 8;
    double ss = 0.0;
    #pragma unroll
    for (int c = 0; c < 8; c++) { double x = v[c]; ss += x*x; }
    const float sc = (float)((double)out_g[i] / sqrt(ss));
    #pragma unroll
    for (int c = 0; c < 8; c++) g_WoutT[(size_t)n*DD*8 + d*8 + c] = v[c] * sc;
}

// ---------------------------------------------------------------------------
// Prep: normalized codebook + cc = sum(c_n^2), replicating fp32 elementwise ops
// ---------------------------------------------------------------------------
__global__ void kp_cb(const float* __restrict__ cb) {
    const int r = blockIdx.x * 256 + threadIdx.x;   // (n, k)
    if (r >= NCB*KK) return;
    const float* v = cb + (size_t)r * 8;
    float ss = 0.f;
    #pragma unroll
    for (int c = 0; c < 8; c++) ss = __fadd_rn(ss, __fmul_rn(v[c], v[c]));
    const float nr = fmaxf(__fsqrt_rn(ss), 1e-12f);
    float cn[8];
    #pragma unroll
    for (int c = 0; c < 8; c++) cn[c] = __fdiv_rn(v[c], nr);
    #pragma unroll
    for (int c = 0; c < 8; c++) g_cbn[(size_t)r*8 + c] = cn[c];
    float s2 = 0.f;
    #pragma unroll
    for (int c = 0; c < 8; c++) s2 = __fadd_rn(s2, __fmul_rn(cn[c], cn[c]));
    g_cc[r] = s2;
}

// ---------------------------------------------------------------------------
// Mega kernel: one thread owns TWO adjacent tokens (2p, 2p+1) through all 9
// stages + final pass. f32x2 lanes = tokens; per-lane op sequences are
// bit-identical to the R6/R8 passing kernels. Tables pre-duplicated in smem;
// wout/ob stored NEGATED (exact under IEEE sign symmetry).
// R10 delta vs R9 (scheduling only): depth-16 u64 double-buffered prefetch in
// the stage streaming loop (restores R8-level in-flight bytes at half the L1
// wavefront cost).
// ---------------------------------------------------------------------------
__global__ void __launch_bounds__(THREADS) k_mega(const float* __restrict__ z,
                                                  const float* __restrict__ in_b,
                                                  const float* __restrict__ out_b,
                                                  const float* __restrict__ cb_raw,
                                                  float* __restrict__ out) {
    extern __shared__ float smf[];
    __shared__ float red[256];

    const int tid = threadIdx.x;
    int p = blockIdx.x * THREADS + tid;
    const int active = (p < NP) ? 1 : 0;
    if (!active) p = NP - 1;      // clones duplicate last pair (identical writes)
    const int token = 2 * p;
    const int b = token >> 13;
    const int t = token & (TT - 1);
    const size_t off = (size_t)b*DD*TT + t;

    unsigned long long* wind = (unsigned long long*)&smf[SM_WIND];
    unsigned long long* wo0d = (unsigned long long*)&smf[SM_WO0D];
    unsigned long long* ob0d = (unsigned long long*)&smf[SM_OB0D];
    unsigned long long* ob1d = (unsigned long long*)&smf[SM_OB1D];

    float zqA0[8] = {0,0,0,0,0,0,0,0}, zqA1[8] = {0,0,0,0,0,0,0,0};
    float zqB0[8] = {0,0,0,0,0,0,0,0}, zqB1[8] = {0,0,0,0,0,0,0,0};
    float lacc = 0.f;

    for (int n = 0; n < NCB; n++) {
        const int nproj = (n == 0) ? 0 : (((n & 1) && n >= 3) ? 2 : 1);
        const int m0 = n - nproj;
        const float* rin = (n <= 1) ? z
                          : ((n == 2 || n == 3 || n == 6 || n == 7) ? (const float*)g_resA
                                                                    : (const float*)g_resB);
        float* wr = nullptr;
        if (n == 1) wr = g_resA;
        else if (n == 3) wr = g_resB;
        else if (n == 5) wr = g_resA;
        else if (n == 7) wr = g_resB;

        __syncthreads();   // previous stage done with smem
        for (int i = tid; i < KK*8; i += THREADS) {
            const int k = i >> 3, c = i & 7;
            smf[SM_CB2 + (k >> 1)*16 + c*2 + (k & 1)] = g_cbn[(size_t)n*KK*8 + i];
        }
        for (int k = tid; k < KK; k += THREADS) smf[SM_CC2 + k] = g_cc[n*KK + k];
        for (int i = tid; i < DD*8; i += THREADS) {
            const float v = g_WinT[(size_t)n*DD*8 + i];
            wind[i] = pk2(v, v);
        }
        if (nproj >= 1) {
            for (int i = tid; i < DD*8; i += THREADS) {
                const float v = -g_WoutT[(size_t)m0*DD*8 + i];
                wo0d[i] = pk2(v, v);
            }
            for (int i = tid; i < DD; i += THREADS) {
                const float v = -out_b[m0*DD + i];
                ob0d[i] = pk2(v, v);
            }
        }
        if (nproj == 2) {
            for (int i = tid; i < DD*8; i += THREADS)
                smf[SM_WO1 + i] = -g_WoutT[(size_t)(m0 + 1)*DD*8 + i];
            for (int i = tid; i < DD; i += THREADS) {
                const float v = -out_b[(m0 + 1)*DD + i];
                ob1d[i] = pk2(v, v);
            }
        }
        __syncthreads();

        unsigned long long zp2[8], za2[8];
        #pragma unroll
        for (int c = 0; c < 8; c++) {
            zp2[c] = (nproj == 2) ? pk2(zqB0[c], zqB1[c]) : pk2(zqA0[c], zqA1[c]);
            za2[c] = pk2(zqA0[c], zqA1[c]);
        }

        // ---- Phase 1: stream residual pair (depth-16 prefetch), projections, z_e ----
        unsigned long long acc[8] = {0,0,0,0,0,0,0,0};
        unsigned long long rbuf[16];
        #pragma unroll
        for (int i = 0; i < 16; i++)
            rbuf[i] = *(const unsigned long long*)(rin + off + (size_t)i*TT);

        for (int d0 = 0; d0 < DD; d0 += 16) {
            unsigned long long rnx[16];
            const bool more = (d0 + 16) < DD;
            if (more) {
                #pragma unroll
                for (int i = 0; i < 16; i++)
                    rnx[i] = *(const unsigned long long*)(rin + off + (size_t)(d0 + 16 + i)*TT);
            }
            #pragma unroll
            for (int i = 0; i < 16; i++) {
                const int d = d0 + i;
                unsigned long long r2 = rbuf[i];
                if (nproj >= 1) {
                    const ulonglong2* w = (const ulonglong2*)(wo0d + d*8);
                    const ulonglong2 q0 = w[0], q1 = w[1], q2 = w[2], q3 = w[3];
                    unsigned long long dt = ffma2(q0.x, zp2[0], 0ull);
                    dt = ffma2(q0.y, zp2[1], dt);
                    dt = ffma2(q1.x, zp2[2], dt);
                    dt = ffma2(q1.y, zp2[3], dt);
                    dt = ffma2(q2.x, zp2[4], dt);
                    dt = ffma2(q2.y, zp2[5], dt);
                    dt = ffma2(q3.x, zp2[6], dt);
                    dt = ffma2(q3.y, zp2[7], dt);
                    dt = fadd2(dt, ob0d[d]);    // = -(dot + ob) exactly
                    r2 = fadd2(r2, dt);         // = rn(r - pr) exactly
                }
                if (nproj == 2) {
                    const float4 wa = *(const float4*)&smf[SM_WO1 + d*8];
                    const float4 wb = *(const float4*)&smf[SM_WO1 + d*8 + 4];
                    unsigned long long dt = ffma2(pk2(wa.x, wa.x), za2[0], 0ull);
                    dt = ffma2(pk2(wa.y, wa.y), za2[1], dt);
                    dt = ffma2(pk2(wa.z, wa.z), za2[2], dt);
                    dt = ffma2(pk2(wa.w, wa.w), za2[3], dt);
                    dt = ffma2(pk2(wb.x, wb.x), za2[4], dt);
                    dt = ffma2(pk2(wb.y, wb.y), za2[5], dt);
                    dt = ffma2(pk2(wb.z, wb.z), za2[6], dt);
                    dt = ffma2(pk2(wb.w, wb.w), za2[7], dt);
                    dt = fadd2(dt, ob1d[d]);
                    r2 = fadd2(r2, dt);
                }
                if (wr) *(unsigned long long*)(wr + off + (size_t)d*TT) = r2;
                const ulonglong2* wi = (const ulonglong2*)(wind + d*8);
                const ulonglong2 a0 = wi[0], a1 = wi[1], a2 = wi[2], a3 = wi[3];
                acc[0] = ffma2(a0.x, r2, acc[0]);
                acc[1] = ffma2(a0.y, r2, acc[1]);
                acc[2] = ffma2(a1.x, r2, acc[2]);
                acc[3] = ffma2(a1.y, r2, acc[3]);
                acc[4] = ffma2(a2.x, r2, acc[4]);
                acc[5] = ffma2(a2.y, r2, acc[5]);
                acc[6] = ffma2(a3.x, r2, acc[6]);
                acc[7] = ffma2(a3.y, r2, acc[7]);
            }
            if (more) {
                #pragma unroll
                for (int i = 0; i < 16; i++) rbuf[i] = rnx[i];
            }
        }

        // ---- Phase 2: z_e per token, normalize (identical scalar ops) ----
        float e0[8], e1[8];
        #pragma unroll
        for (int c = 0; c < 8; c++) {
            upk2(acc[c], e0[c], e1[c]);
            const float vb = __ldg(in_b + n*8 + c);
            e0[c] = __fadd_rn(e0[c], vb);
            e1[c] = __fadd_rn(e1[c], vb);
        }

        unsigned long long enA[8], enB[8], eepA, eepB;
        {
            float ssq = 0.f;
            #pragma unroll
            for (int c = 0; c < 8; c++) ssq = __fadd_rn(ssq, __fmul_rn(e0[c], e0[c]));
            const float rho = fmaxf(__fsqrt_rn(ssq), 1e-12f);
            float en[8], ee = 0.f;
            #pragma unroll
            for (int c = 0; c < 8; c++) en[c] = __fdiv_rn(e0[c], rho);
            #pragma unroll
            for (int c = 0; c < 8; c++) ee = __fadd_rn(ee, __fmul_rn(en[c], en[c]));
            #pragma unroll
            for (int c = 0; c < 8; c++) enA[c] = pk2(en[c], en[c]);
            eepA = pk2(ee, ee);
        }
        {
            float ssq = 0.f;
            #pragma unroll
            for (int c = 0; c < 8; c++) ssq = __fadd_rn(ssq, __fmul_rn(e1[c], e1[c]));
            const float rho = fmaxf(__fsqrt_rn(ssq), 1e-12f);
            float en[8], ee = 0.f;
            #pragma unroll
            for (int c = 0; c < 8; c++) en[c] = __fdiv_rn(e1[c], rho);
            #pragma unroll
            for (int c = 0; c < 8; c++) ee = __fadd_rn(ee, __fmul_rn(en[c], en[c]));
            #pragma unroll
            for (int c = 0; c < 8; c++) enB[c] = pk2(en[c], en[c]);
            eepB = pk2(ee, ee);
        }
        const unsigned long long m2 = pk2(-2.f, -2.f);

        // ---- argmin: both tokens share the codebook LDS; per-token math and
        //      4-chain first-wins merge identical to R8 ----
        float aA = 3.4e38f, aB = 3.4e38f, aC = 3.4e38f, aD = 3.4e38f;
        int   jA = 0, jB = 0, jC = 0, jD = 0;
        float bA_ = 3.4e38f, bB_ = 3.4e38f, bC_ = 3.4e38f, bD_ = 3.4e38f;
        int   kA = 0, kB = 0, kC = 0, kD = 0;
        const unsigned long long* cbu = (const unsigned long long*)&smf[SM_CB2];
        const unsigned long long* ccu = (const unsigned long long*)&smf[SM_CC2];
        for (int k2 = 0; k2 < KK/2; k2 += 2) {
            const ulonglong2 ca0 = *(const ulonglong2*)(cbu + k2*8);
            const ulonglong2 cb0 = *(const ulonglong2*)(cbu + k2*8 + 2);
            const ulonglong2 cc0 = *(const ulonglong2*)(cbu + k2*8 + 4);
            const ulonglong2 cd0 = *(const ulonglong2*)(cbu + k2*8 + 6);
            const ulonglong2 ca1 = *(const ulonglong2*)(cbu + (k2+1)*8);
            const ulonglong2 cb1 = *(const ulonglong2*)(cbu + (k2+1)*8 + 2);
            const ulonglong2 cc1 = *(const ulonglong2*)(cbu + (k2+1)*8 + 4);
            const ulonglong2 cd1 = *(const ulonglong2*)(cbu + (k2+1)*8 + 6);
            const unsigned long long ccv0 = ccu[k2], ccv1 = ccu[k2+1];
            // token A
            {
                unsigned long long dp0 = fmul2(enA[0], ca0.x);
                unsigned long long dp1 = fmul2(enA[0], ca1.x);
                dp0 = ffma2(enA[1], ca0.y, dp0);  dp1 = ffma2(enA[1], ca1.y, dp1);
                dp0 = ffma2(enA[2], cb0.x, dp0);  dp1 = ffma2(enA[2], cb1.x, dp1);
                dp0 = ffma2(enA[3], cb0.y, dp0);  dp1 = ffma2(enA[3], cb1.y, dp1);
                dp0 = ffma2(enA[4], cc0.x, dp0);  dp1 = ffma2(enA[4], cc1.x, dp1);
                dp0 = ffma2(enA[5], cc0.y, dp0);  dp1 = ffma2(enA[5], cc1.y, dp1);
                dp0 = ffma2(enA[6], cd0.x, dp0);  dp1 = ffma2(enA[6], cd1.x, dp1);
                dp0 = ffma2(enA[7], cd0.y, dp0);  dp1 = ffma2(enA[7], cd1.y, dp1);
                const unsigned long long t0 = ffma2(m2, dp0, eepA);
                const unsigned long long t1 = ffma2(m2, dp1, eepA);
                const unsigned long long di0 = fadd2(t0, ccv0);
                const unsigned long long di1 = fadd2(t1, ccv1);
                float d0v, d1v, d2v, d3v;
                upk2(di0, d0v, d1v); upk2(di1, d2v, d3v);
                if (d0v < aA) { aA = d0v; jA = 2*k2; }
                if (d1v < aB) { aB = d1v; jB = 2*k2 + 1; }
                if (d2v < aC) { aC = d2v; jC = 2*k2 + 2; }
                if (d3v < aD) { aD = d3v; jD = 2*k2 + 3; }
            }
            // token B
            {
                unsigned long long dp0 = fmul2(enB[0], ca0.x);
                unsigned long long dp1 = fmul2(enB[0], ca1.x);
                dp0 = ffma2(enB[1], ca0.y, dp0);  dp1 = ffma2(enB[1], ca1.y, dp1);
                dp0 = ffma2(enB[2], cb0.x, dp0);  dp1 = ffma2(enB[2], cb1.x, dp1);
                dp0 = ffma2(enB[3], cb0.y, dp0);  dp1 = ffma2(enB[3], cb1.y, dp1);
                dp0 = ffma2(enB[4], cc0.x, dp0);  dp1 = ffma2(enB[4], cc1.x, dp1);
                dp0 = ffma2(enB[5], cc0.y, dp0);  dp1 = ffma2(enB[5], cc1.y, dp1);
                dp0 = ffma2(enB[6], cd0.x, dp0);  dp1 = ffma2(enB[6], cd1.x, dp1);
                dp0 = ffma2(enB[7], cd0.y, dp0);  dp1 = ffma2(enB[7], cd1.y, dp1);
                const unsigned long long t0 = ffma2(m2, dp0, eepB);
                const unsigned long long t1 = ffma2(m2, dp1, eepB);
                const unsigned long long di0 = fadd2(t0, ccv0);
                const unsigned long long di1 = fadd2(t1, ccv1);
                float d0v, d1v, d2v, d3v;
                upk2(di0, d0v, d1v); upk2(di1, d2v, d3v);
                if (d0v < bA_) { bA_ = d0v; kA = 2*k2; }
                if (d1v < bB_) { bB_ = d1v; kB = 2*k2 + 1; }
                if (d2v < bC_) { bC_ = d2v; kC = 2*k2 + 2; }
                if (d3v < bD_) { bD_ = d3v; kD = 2*k2 + 3; }
            }
        }
        float best0 = aA; int bi0 = jA;
        if (aB < best0 || (aB == best0 && jB < bi0)) { best0 = aB; bi0 = jB; }
        if (aC < best0 || (aC == best0 && jC < bi0)) { best0 = aC; bi0 = jC; }
        if (aD < best0 || (aD == best0 && jD < bi0)) { best0 = aD; bi0 = jD; }
        float best1 = bA_; int bi1 = kA;
        if (bB_ < best1 || (bB_ == best1 && kB < bi1)) { best1 = bB_; bi1 = kB; }
        if (bC_ < best1 || (bC_ == best1 && kC < bi1)) { best1 = bC_; bi1 = kC; }
        if (bD_ < best1 || (bD_ == best1 && kD < bi1)) { best1 = bD_; bi1 = kD; }

        // ---- Phase 3: winners, straight-through, outputs ----
        const float* q0p = cb_raw + ((size_t)n*KK + bi0)*8;
        const float* q1p = cb_raw + ((size_t)n*KK + bi1)*8;
        const float4 qa0 = __ldg((const float4*)q0p);
        const float4 qa1 = __ldg((const float4*)(q0p + 4));
        const float4 qb0 = __ldg((const float4*)q1p);
        const float4 qb1 = __ldg((const float4*)(q1p + 4));
        const float q0[8] = {qa0.x, qa0.y, qa0.z, qa0.w, qa1.x, qa1.y, qa1.z, qa1.w};
        const float q1[8] = {qb0.x, qb0.y, qb0.z, qb0.w, qb1.x, qb1.y, qb1.z, qb1.w};

        #pragma unroll
        for (int c = 0; c < 8; c++) {
            const float dl0 = __fsub_rn(e0[c], q0[c]);
            lacc = fmaf(dl0, dl0, lacc);
            const float dl1 = __fsub_rn(e1[c], q1[c]);
            lacc = fmaf(dl1, dl1, lacc);
            zqB0[c] = zqA0[c]; zqB1[c] = zqA1[c];
            zqA0[c] = __fadd_rn(e0[c], __fsub_rn(q0[c], e0[c]));
            zqA1[c] = __fadd_rn(e1[c], __fsub_rn(q1[c], e1[c]));
        }

        *(float2*)&out[OFF_CODES + (size_t)b*NCB*TT + (size_t)n*TT + t] =
            make_float2((float)bi0, (float)bi1);
        #pragma unroll
        for (int c = 0; c < 8; c++)
            *(float2*)&out[OFF_LAT + (size_t)b*CN*TT + (size_t)(n*8 + c)*TT + t] =
                make_float2(e0[c], e1[c]);
    }

    // ---- Final pass: res7(B) -> fly proj7 (zqB) -> proj8 (zqA) -> out = z - res9 ----
    __syncthreads();
    for (int i = tid; i < DD*8; i += THREADS) {
        const float v7 = -g_WoutT[(size_t)7*DD*8 + i];
        wo0d[i] = pk2(v7, v7);
        const float v8 = -g_WoutT[(size_t)8*DD*8 + i];
        wind[i] = pk2(v8, v8);
    }
    for (int i = tid; i < DD; i += THREADS) {
        const float v7 = -out_b[7*DD + i];
        ob0d[i] = pk2(v7, v7);
        const float v8 = -out_b[8*DD + i];
        ob1d[i] = pk2(v8, v8);
    }
    __syncthreads();

    {
        unsigned long long zb2[8], za2[8];
        #pragma unroll
        for (int c = 0; c < 8; c++) {
            zb2[c] = pk2(zqB0[c], zqB1[c]);
            za2[c] = pk2(zqA0[c], zqA1[c]);
        }
        const unsigned long long SGN = 0x8000000080000000ull;
        unsigned long long rb[8], zb[8];
        #pragma unroll
        for (int i = 0; i < 8; i++) {
            rb[i] = *(const unsigned long long*)((const float*)g_resB + off + (size_t)i*TT);
            zb[i] = *(const unsigned long long*)(z + off + (size_t)i*TT);
        }
        for (int d0 = 0; d0 < DD; d0 += 8) {
            unsigned long long rn_[8], zn_[8];
            const bool more = (d0 + 8) < DD;
            if (more) {
                #pragma unroll
                for (int i = 0; i < 8; i++) {
                    rn_[i] = *(const unsigned long long*)((const float*)g_resB + off + (size_t)(d0 + 8 + i)*TT);
                    zn_[i] = *(const unsigned long long*)(z + off + (size_t)(d0 + 8 + i)*TT);
                }
            }
            #pragma unroll
            for (int i = 0; i < 8; i++) {
                const int d = d0 + i;
                unsigned long long r2 = rb[i];
                {   // proj7 with zqB
                    const ulonglong2* w = (const ulonglong2*)(wo0d + d*8);
                    const ulonglong2 p0 = w[0], p1 = w[1], p2 = w[2], p3 = w[3];
                    unsigned long long dt = ffma2(p0.x, zb2[0], 0ull);
                    dt = ffma2(p0.y, zb2[1], dt);
                    dt = ffma2(p1.x, zb2[2], dt);
                    dt = ffma2(p1.y, zb2[3], dt);
                    dt = ffma2(p2.x, zb2[4], dt);
                    dt = ffma2(p2.y, zb2[5], dt);
                    dt = ffma2(p3.x, zb2[6], dt);
                    dt = ffma2(p3.y, zb2[7], dt);
                    dt = fadd2(dt, ob0d[d]);
                    r2 = fadd2(r2, dt);
                }
                {   // proj8 with zqA
                    const ulonglong2* w = (const ulonglong2*)(wind + d*8);
                    const ulonglong2 p0 = w[0], p1 = w[1], p2 = w[2], p3 = w[3];
                    unsigned long long dt = ffma2(p0.x, za2[0], 0ull);
                    dt = ffma2(p0.y, za2[1], dt);
                    dt = ffma2(p1.x, za2[2], dt);
                    dt = ffma2(p1.y, za2[3], dt);
                    dt = ffma2(p2.x, za2[4], dt);
                    dt = ffma2(p2.y, za2[5], dt);
                    dt = ffma2(p3.x, za2[6], dt);
                    dt = ffma2(p3.y, za2[7], dt);
                    dt = fadd2(dt, ob1d[d]);
                    r2 = fadd2(r2, dt);
                }
                // out = rn(z - r9) == fadd2(z, -r9) exactly
                *(unsigned long long*)&out[off + (size_t)d*TT] = fadd2(zb[i], r2 ^ SGN);
            }
            if (more) {
                #pragma unroll
                for (int i = 0; i < 8; i++) { rb[i] = rn_[i]; zb[i] = zn_[i]; }
            }
        }
    }

    // ---- loss partial (clones contribute 0) ----
    red[tid] = active ? lacc : 0.f;
    if (tid < 256 - THREADS) red[THREADS + tid] = 0.f;
    __syncthreads();
    for (int s = 128; s > 0; s >>= 1) {
        if (tid < s) red[tid] += red[tid + s];
        __syncthreads();
    }
    if (tid == 0) g_lpart[blockIdx.x] = red[0];
}

// ---------------------------------------------------------------------------
// Deterministic loss reduce in fp64: cl == cbl (identical forward values)
// ---------------------------------------------------------------------------
__global__ void k_loss(float* __restrict__ out) {
    if (threadIdx.x != 0 || blockIdx.x != 0) return;
    double s = 0.0;
    for (int i = 0; i < NBLK; i++) s += (double)g_lpart[i];
    const float v = (float)(s / 524288.0);   // per-stage mean over B*C*T, summed
    out[OFF_CL]     = v;
    out[OFF_CL + 1] = v;
}

// ---------------------------------------------------------------------------
extern "C" void kernel_launch(void* const* d_in, const int* in_sizes, int n_in,
                              void* d_out, int out_size) {
    (void)in_sizes; (void)n_in; (void)out_size;
    const float* z     = (const float*)d_in[0];
    const float* in_v  = (const float*)d_in[1];
    const float* in_g  = (const float*)d_in[2];
    const float* in_b  = (const float*)d_in[3];
    const float* out_v = (const float*)d_in[4];
    const float* out_g = (const float*)d_in[5];
    const float* out_b = (const float*)d_in[6];
    const float* cb    = (const float*)d_in[7];
    float* out = (float*)d_out;

    cudaFuncSetAttribute(k_mega, cudaFuncAttributeMaxDynamicSharedMemorySize, SMEM_TOT);

    kp_win  <<<72, 256>>>(in_v, in_g);
    kp_wout <<<(NCB*DD + 255)/256, 256>>>(out_v, out_g);
    kp_cb   <<<(NCB*KK + 255)/256, 256>>>(cb);

    k_mega <<<NBLK, THREADS, SMEM_TOT>>>(z, in_b, out_b, cb, out);
    k_loss <<<1, 32>>>(out);
}

// round 11
// speedup vs baseline: 1.2751x; 1.1077x over previous
#include <cuda_runtime.h>
#include <cstdint>

// Problem dims
#define BB 8
#define DD 1024
#define TT 8192
#define NCB 9
#define KK 1024
#define NT (BB*TT)        // 65536 tokens
#define CN (NCB*8)        // 72

// Output layout (float32, tuple flattened in order)
#define OFF_CODES ((size_t)BB*DD*TT)                  // 67108864
#define OFF_LAT   (OFF_CODES + (size_t)BB*NCB*TT)     // 67698688
#define OFF_CL    (OFF_LAT + (size_t)BB*CN*TT)        // 72417280

#define THREADS 224
#define NBLK 304          // 304*224 = 68096 >= 65536 tokens; 2 blocks/SM

// Dynamic smem: OVERLAY — streaming tables and argmin tables share the region.
// Streaming overlay: win[8192] wo0[8192] wo1[8192] ob0[1024] ob1[1024] = 26624 f
// Argmin overlay:    cb2[8192] cc2[1024]                                =  9216 f
#define SM_WIN 0          // 8192 f : win [d][8] (plain)
#define SM_WO0 8192       // 8192 f : wout m0 [d][8] (plain)
#define SM_WO1 16384      // 8192 f : wout m0+1 [d][8] (plain)
#define SM_OB0 24576      // 1024 f
#define SM_OB1 25600      // 1024 f
#define SM_CB2 0          // 8192 f : codebook pair-interleaved (overlays win/wo0)
#define SM_CC2 8192       // 1024 f : (overlays wo0 tail)
#define SMEM_TOT (26624*4)   // 106496 bytes -> 2 blocks/SM

// Scratch (__device__ globals: allowed; no runtime allocation)
__device__ float g_resA[(size_t)BB*DD*TT];           // checkpoint buffer A (res1, res5)
__device__ float g_resB[(size_t)BB*DD*TT];           // checkpoint buffer B (res3, res7)
__device__ __align__(16) float g_WinT[NCB*DD*8];     // [n][d][c]
__device__ __align__(16) float g_WoutT[NCB*DD*8];    // [n][d][c]
__device__ __align__(16) float g_cbn[NCB*KK*8];      // normalized codebook (ref fp32 semantics)
__device__ __align__(16) float g_cc[NCB*KK];         // sum(c_n*c_n)
__device__ __align__(16) float g_lpart[NBLK];

// ---------------------------------------------------------------------------
// f32x2 packed helpers (each lane an exact IEEE fp32 op)
// ---------------------------------------------------------------------------
__device__ __forceinline__ unsigned long long pk2(float lo, float hi) {
    unsigned long long r;
    asm("mov.b64 %0, {%1, %2};" : "=l"(r) : "f"(lo), "f"(hi));
    return r;
}
__device__ __forceinline__ void upk2(unsigned long long v, float& lo, float& hi) {
    asm("mov.b64 {%0, %1}, %2;" : "=f"(lo), "=f"(hi) : "l"(v));
}
__device__ __forceinline__ unsigned long long ffma2(unsigned long long a, unsigned long long b, unsigned long long c) {
    unsigned long long r;
    asm("fma.rn.f32x2 %0, %1, %2, %3;" : "=l"(r) : "l"(a), "l"(b), "l"(c));
    return r;
}
__device__ __forceinline__ unsigned long long fmul2(unsigned long long a, unsigned long long b) {
    unsigned long long r;
    asm("mul.rn.f32x2 %0, %1, %2;" : "=l"(r) : "l"(a), "l"(b));
    return r;
}
__device__ __forceinline__ unsigned long long fadd2(unsigned long long a, unsigned long long b) {
    unsigned long long r;
    asm("add.rn.f32x2 %0, %1, %2;" : "=l"(r) : "l"(a), "l"(b));
    return r;
}

// ---------------------------------------------------------------------------
// Prep: weight-norm input rows (fp64 norms), store [n][d][8c]
// ---------------------------------------------------------------------------
__global__ void kp_win(const float* __restrict__ in_v, const float* __restrict__ in_g) {
    const int row = blockIdx.x;               // 0..71 = n*8 + c
    const int n = row >> 3, c = row & 7;
    const float* src = in_v + (size_t)row * DD;
    __shared__ double red[256];
    double ss = 0.0;
    for (int d = threadIdx.x; d < DD; d += 256) { double v = src[d]; ss += v*v; }
    red[threadIdx.x] = ss; __syncthreads();
    for (int s = 128; s > 0; s >>= 1) {
        if (threadIdx.x < s) red[threadIdx.x] += red[threadIdx.x + s];
        __syncthreads();
    }
    const float scale = (float)((double)in_g[row] / sqrt(red[0]));
    for (int d = threadIdx.x; d < DD; d += 256)
        g_WinT[(size_t)n*DD*8 + d*8 + c] = src[d] * scale;
}

// ---------------------------------------------------------------------------
// Prep: weight-norm output rows (norm over C=8, fp64), store [n][d][8c]
// ---------------------------------------------------------------------------
__global__ void kp_wout(const float* __restrict__ out_v, const float* __restrict__ out_g) {
    const int i = blockIdx.x * 256 + threadIdx.x;   // (n, d)
    if (i >= NCB*DD) return;
    const int n = i / DD, d = i - n*DD;
    const float* v = out_v + (size_t)i * 8;
    double ss = 0.0;
    #pragma unroll
    for (int c = 0; c < 8; c++) { double x = v[c]; ss += x*x; }
    const float sc = (float)((double)out_g[i] / sqrt(ss));
    #pragma unroll
    for (int c = 0; c < 8; c++) g_WoutT[(size_t)n*DD*8 + d*8 + c] = v[c] * sc;
}

// ---------------------------------------------------------------------------
// Prep: normalized codebook + cc = sum(c_n^2), replicating fp32 elementwise ops
// ---------------------------------------------------------------------------
__global__ void kp_cb(const float* __restrict__ cb) {
    const int r = blockIdx.x * 256 + threadIdx.x;   // (n, k)
    if (r >= NCB*KK) return;
    const float* v = cb + (size_t)r * 8;
    float ss = 0.f;
    #pragma unroll
    for (int c = 0; c < 8; c++) ss = __fadd_rn(ss, __fmul_rn(v[c], v[c]));
    const float nr = fmaxf(__fsqrt_rn(ss), 1e-12f);
    float cn[8];
    #pragma unroll
    for (int c = 0; c < 8; c++) cn[c] = __fdiv_rn(v[c], nr);
    #pragma unroll
    for (int c = 0; c < 8; c++) g_cbn[(size_t)r*8 + c] = cn[c];
    float s2 = 0.f;
    #pragma unroll
    for (int c = 0; c < 8; c++) s2 = __fadd_rn(s2, __fmul_rn(cn[c], cn[c]));
    g_cc[r] = s2;
}

// ---------------------------------------------------------------------------
// Mega kernel: thread owns ONE token through all 9 stages + final pass.
// Arithmetic bit-identical to the R8 passing kernel (same values, op order).
// R11 delta (scheduling only): smem overlay — streaming tables (win/wout/ob)
// and argmin tables (cb/cc) share one 104KB region with a barrier between the
// phases -> 2 co-resident blocks per SM, so one block's DRAM streaming
// overlaps the other block's argmin compute.
// ---------------------------------------------------------------------------
__global__ void __launch_bounds__(THREADS, 2) k_mega(const float* __restrict__ z,
                                                     const float* __restrict__ in_b,
                                                     const float* __restrict__ out_b,
                                                     const float* __restrict__ cb_raw,
                                                     float* __restrict__ out) {
    extern __shared__ float smf[];
    __shared__ float red[256];

    const int tid = threadIdx.x;
    int token = blockIdx.x * THREADS + tid;
    const int active = (token < NT) ? 1 : 0;
    if (!active) token = NT - 1;   // clones duplicate last token (identical writes)
    const int b = token >> 13;
    const int t = token & (TT - 1);
    const size_t off = (size_t)b*DD*TT + t;

    float zqA[8] = {0,0,0,0,0,0,0,0};   // zqst of stage n-1
    float zqB[8] = {0,0,0,0,0,0,0,0};   // zqst of stage n-2
    float lacc = 0.f;

    for (int n = 0; n < NCB; n++) {
        const int nproj = (n == 0) ? 0 : (((n & 1) && n >= 3) ? 2 : 1);
        const int m0 = n - nproj;
        const float* rin = (n <= 1) ? z
                          : ((n == 2 || n == 3 || n == 6 || n == 7) ? (const float*)g_resA
                                                                    : (const float*)g_resB);
        float* wr = nullptr;
        if (n == 1) wr = g_resA;
        else if (n == 3) wr = g_resB;
        else if (n == 5) wr = g_resA;
        else if (n == 7) wr = g_resB;

        // ---- load STREAMING tables into the overlay region ----
        __syncthreads();   // previous stage's argmin done with smem
        for (int i = tid; i < DD*8; i += THREADS) smf[SM_WIN + i] = g_WinT[(size_t)n*DD*8 + i];
        if (nproj >= 1) {
            for (int i = tid; i < DD*8; i += THREADS)
                smf[SM_WO0 + i] = g_WoutT[(size_t)m0*DD*8 + i];
            for (int i = tid; i < DD; i += THREADS)
                smf[SM_OB0 + i] = out_b[m0*DD + i];
        }
        if (nproj == 2) {
            for (int i = tid; i < DD*8; i += THREADS)
                smf[SM_WO1 + i] = g_WoutT[(size_t)(m0 + 1)*DD*8 + i];
            for (int i = tid; i < DD; i += THREADS)
                smf[SM_OB1 + i] = out_b[(m0 + 1)*DD + i];
        }
        __syncthreads();

        // first-projection operand: zqst_{m0} = (nproj==2 ? zqB : zqA)
        float zp[8];
        #pragma unroll
        for (int c = 0; c < 8; c++) zp[c] = (nproj == 2) ? zqB[c] : zqA[c];

        // ---- Phase 1: stream residual, apply projections, accumulate z_e ----
        unsigned long long accp[4] = {0ull, 0ull, 0ull, 0ull};
        float rbuf[16];
        #pragma unroll
        for (int i = 0; i < 16; i++) rbuf[i] = rin[off + (size_t)i*TT];

        for (int d0 = 0; d0 < DD; d0 += 16) {
            float rnx[16];
            const bool more = (d0 + 16) < DD;
            if (more) {
                #pragma unroll
                for (int i = 0; i < 16; i++)
                    rnx[i] = rin[off + (size_t)(d0 + 16 + i)*TT];
            }
            #pragma unroll
            for (int i = 0; i < 16; i++) {
                const int d = d0 + i;
                float r = rbuf[i];
                if (nproj >= 1) {
                    const float4 wa = *(const float4*)&smf[SM_WO0 + d*8];
                    const float4 wb = *(const float4*)&smf[SM_WO0 + d*8 + 4];
                    float dt = 0.f;
                    dt = fmaf(wa.x, zp[0], dt);
                    dt = fmaf(wa.y, zp[1], dt);
                    dt = fmaf(wa.z, zp[2], dt);
                    dt = fmaf(wa.w, zp[3], dt);
                    dt = fmaf(wb.x, zp[4], dt);
                    dt = fmaf(wb.y, zp[5], dt);
                    dt = fmaf(wb.z, zp[6], dt);
                    dt = fmaf(wb.w, zp[7], dt);
                    const float pr = __fadd_rn(dt, smf[SM_OB0 + d]);
                    r = __fsub_rn(r, pr);
                }
                if (nproj == 2) {
                    const float4 wa = *(const float4*)&smf[SM_WO1 + d*8];
                    const float4 wb = *(const float4*)&smf[SM_WO1 + d*8 + 4];
                    float dt = 0.f;
                    dt = fmaf(wa.x, zqA[0], dt);
                    dt = fmaf(wa.y, zqA[1], dt);
                    dt = fmaf(wa.z, zqA[2], dt);
                    dt = fmaf(wa.w, zqA[3], dt);
                    dt = fmaf(wb.x, zqA[4], dt);
                    dt = fmaf(wb.y, zqA[5], dt);
                    dt = fmaf(wb.z, zqA[6], dt);
                    dt = fmaf(wb.w, zqA[7], dt);
                    const float pr = __fadd_rn(dt, smf[SM_OB1 + d]);
                    r = __fsub_rn(r, pr);
                }
                if (wr) wr[off + (size_t)d*TT] = r;
                // z_e accumulation: win pairs read directly as packed f32x2
                const ulonglong2 w01 = *(const ulonglong2*)&smf[SM_WIN + d*8];
                const ulonglong2 w23 = *(const ulonglong2*)&smf[SM_WIN + d*8 + 4];
                const unsigned long long rp = pk2(r, r);
                accp[0] = ffma2(w01.x, rp, accp[0]);
                accp[1] = ffma2(w01.y, rp, accp[1]);
                accp[2] = ffma2(w23.x, rp, accp[2]);
                accp[3] = ffma2(w23.y, rp, accp[3]);
            }
            if (more) {
                #pragma unroll
                for (int i = 0; i < 16; i++) rbuf[i] = rnx[i];
            }
        }

        // ---- swap overlay: load ARGMIN tables (cb pair-interleaved + cc) ----
        __syncthreads();   // streaming done reading win/wout/ob
        for (int i = tid; i < KK*8; i += THREADS) {
            const int k = i >> 3, c = i & 7;
            smf[SM_CB2 + (k >> 1)*16 + c*2 + (k & 1)] = g_cbn[(size_t)n*KK*8 + i];
        }
        for (int k = tid; k < KK; k += THREADS) smf[SM_CC2 + k] = g_cc[n*KK + k];
        __syncthreads();

        // ---- Phase 2: z_e, normalize (identical ops) ----
        float e[8];
        upk2(accp[0], e[0], e[1]); upk2(accp[1], e[2], e[3]);
        upk2(accp[2], e[4], e[5]); upk2(accp[3], e[6], e[7]);
        #pragma unroll
        for (int c = 0; c < 8; c++) e[c] = __fadd_rn(e[c], __ldg(in_b + n*8 + c));

        float ssq = 0.f;
        #pragma unroll
        for (int c = 0; c < 8; c++) ssq = __fadd_rn(ssq, __fmul_rn(e[c], e[c]));
        const float rho = fmaxf(__fsqrt_rn(ssq), 1e-12f);
        float en[8];
        #pragma unroll
        for (int c = 0; c < 8; c++) en[c] = __fdiv_rn(e[c], rho);
        float ee = 0.f;
        #pragma unroll
        for (int c = 0; c < 8; c++) ee = __fadd_rn(ee, __fmul_rn(en[c], en[c]));

        unsigned long long en2[8];
        #pragma unroll
        for (int c = 0; c < 8; c++) en2[c] = pk2(en[c], en[c]);
        const unsigned long long eep = pk2(ee, ee);
        const unsigned long long m2  = pk2(-2.f, -2.f);

        // ---- argmin: per-k dist bit-identical; 4 chains, exact first-wins merge ----
        float bA = 3.4e38f, bBv = 3.4e38f, bC = 3.4e38f, bD = 3.4e38f;
        int   iA = 0, iB = 0, iC = 0, iD = 0;
        const unsigned long long* cbu = (const unsigned long long*)&smf[SM_CB2];
        const unsigned long long* ccu = (const unsigned long long*)&smf[SM_CC2];
        #pragma unroll 2
        for (int k2 = 0; k2 < KK/2; k2 += 2) {
            const ulonglong2 ca0 = *(const ulonglong2*)(cbu + k2*8);
            const ulonglong2 cb0 = *(const ulonglong2*)(cbu + k2*8 + 2);
            const ulonglong2 cc0 = *(const ulonglong2*)(cbu + k2*8 + 4);
            const ulonglong2 cd0 = *(const ulonglong2*)(cbu + k2*8 + 6);
            const ulonglong2 ca1 = *(const ulonglong2*)(cbu + (k2+1)*8);
            const ulonglong2 cb1 = *(const ulonglong2*)(cbu + (k2+1)*8 + 2);
            const ulonglong2 cc1 = *(const ulonglong2*)(cbu + (k2+1)*8 + 4);
            const ulonglong2 cd1 = *(const ulonglong2*)(cbu + (k2+1)*8 + 6);
            unsigned long long dp0 = fmul2(en2[0], ca0.x);
            unsigned long long dp1 = fmul2(en2[0], ca1.x);
            dp0 = ffma2(en2[1], ca0.y, dp0);  dp1 = ffma2(en2[1], ca1.y, dp1);
            dp0 = ffma2(en2[2], cb0.x, dp0);  dp1 = ffma2(en2[2], cb1.x, dp1);
            dp0 = ffma2(en2[3], cb0.y, dp0);  dp1 = ffma2(en2[3], cb1.y, dp1);
            dp0 = ffma2(en2[4], cc0.x, dp0);  dp1 = ffma2(en2[4], cc1.x, dp1);
            dp0 = ffma2(en2[5], cc0.y, dp0);  dp1 = ffma2(en2[5], cc1.y, dp1);
            dp0 = ffma2(en2[6], cd0.x, dp0);  dp1 = ffma2(en2[6], cd1.x, dp1);
            dp0 = ffma2(en2[7], cd0.y, dp0);  dp1 = ffma2(en2[7], cd1.y, dp1);
            const unsigned long long t0 = ffma2(m2, dp0, eep);
            const unsigned long long t1 = ffma2(m2, dp1, eep);
            const unsigned long long di0 = fadd2(t0, ccu[k2]);
            const unsigned long long di1 = fadd2(t1, ccu[k2+1]);
            float d0v, d1v, d2v, d3v;
            upk2(di0, d0v, d1v); upk2(di1, d2v, d3v);
            if (d0v < bA)  { bA = d0v;  iA = 2*k2; }
            if (d1v < bBv) { bBv = d1v; iB = 2*k2 + 1; }
            if (d2v < bC)  { bC = d2v;  iC = 2*k2 + 2; }
            if (d3v < bD)  { bD = d3v;  iD = 2*k2 + 3; }
        }
        float best = bA; int bi = iA;
        if (bBv < best || (bBv == best && iB < bi)) { best = bBv; bi = iB; }
        if (bC  < best || (bC  == best && iC < bi)) { best = bC;  bi = iC; }
        if (bD  < best || (bD  == best && iD < bi)) { best = bD;  bi = iD; }

        // ---- Phase 3: winner, straight-through, outputs ----
        const float* qsrc = cb_raw + ((size_t)n*KK + bi)*8;
        const float4 q0 = __ldg((const float4*)qsrc);
        const float4 q1 = __ldg((const float4*)(qsrc + 4));
        const float q[8] = {q0.x, q0.y, q0.z, q0.w, q1.x, q1.y, q1.z, q1.w};

        float zst[8];
        #pragma unroll
        for (int c = 0; c < 8; c++) {
            const float dl = __fsub_rn(e[c], q[c]);
            lacc = fmaf(dl, dl, lacc);
            zst[c] = __fadd_rn(e[c], __fsub_rn(q[c], e[c]));   // z_e + (z_q - z_e)
        }

        out[OFF_CODES + (size_t)b*NCB*TT + (size_t)n*TT + t] = (float)bi;
        #pragma unroll
        for (int c = 0; c < 8; c++)
            out[OFF_LAT + (size_t)b*CN*TT + (size_t)(n*8 + c)*TT + t] = e[c];

        #pragma unroll
        for (int c = 0; c < 8; c++) { zqB[c] = zqA[c]; zqA[c] = zst[c]; }
    }

    // ---- Final pass: res7(B) -> fly res8 (proj7, zqB) -> res9 (proj8, zqA) ----
    __syncthreads();
    for (int i = tid; i < DD*8; i += THREADS) {
        smf[SM_WO0 + i] = g_WoutT[(size_t)7*DD*8 + i];
        smf[SM_WO1 + i] = g_WoutT[(size_t)8*DD*8 + i];
    }
    for (int i = tid; i < DD; i += THREADS) {
        smf[SM_OB0 + i] = out_b[7*DD + i];
        smf[SM_OB1 + i] = out_b[8*DD + i];
    }
    __syncthreads();

    {
        float rb[8], zb[8];
        #pragma unroll
        for (int i = 0; i < 8; i++) {
            rb[i] = g_resB[off + (size_t)i*TT];
            zb[i] = __ldg(z + off + (size_t)i*TT);
        }
        for (int d0 = 0; d0 < DD; d0 += 8) {
            float rn_[8], zn_[8];
            const bool more = (d0 + 8) < DD;
            if (more) {
                #pragma unroll
                for (int i = 0; i < 8; i++) {
                    rn_[i] = g_resB[off + (size_t)(d0 + 8 + i)*TT];
                    zn_[i] = __ldg(z + off + (size_t)(d0 + 8 + i)*TT);
                }
            }
            #pragma unroll
            for (int i = 0; i < 8; i++) {
                const int d = d0 + i;
                float r = rb[i];
                {   // proj7 (exactly what stage 8 computed on the fly)
                    const float4 wa = *(const float4*)&smf[SM_WO0 + d*8];
                    const float4 wb = *(const float4*)&smf[SM_WO0 + d*8 + 4];
                    float dt = 0.f;
                    dt = fmaf(wa.x, zqB[0], dt);
                    dt = fmaf(wa.y, zqB[1], dt);
                    dt = fmaf(wa.z, zqB[2], dt);
                    dt = fmaf(wa.w, zqB[3], dt);
                    dt = fmaf(wb.x, zqB[4], dt);
                    dt = fmaf(wb.y, zqB[5], dt);
                    dt = fmaf(wb.z, zqB[6], dt);
                    dt = fmaf(wb.w, zqB[7], dt);
                    const float pr = __fadd_rn(dt, smf[SM_OB0 + d]);
                    r = __fsub_rn(r, pr);
                }
                {   // proj8
                    const float4 wa = *(const float4*)&smf[SM_WO1 + d*8];
                    const float4 wb = *(const float4*)&smf[SM_WO1 + d*8 + 4];
                    float dt = 0.f;
                    dt = fmaf(wa.x, zqA[0], dt);
                    dt = fmaf(wa.y, zqA[1], dt);
                    dt = fmaf(wa.z, zqA[2], dt);
                    dt = fmaf(wa.w, zqA[3], dt);
                    dt = fmaf(wb.x, zqA[4], dt);
                    dt = fmaf(wb.y, zqA[5], dt);
                    dt = fmaf(wb.z, zqA[6], dt);
                    dt = fmaf(wb.w, zqA[7], dt);
                    const float pr = __fadd_rn(dt, smf[SM_OB1 + d]);
                    r = __fsub_rn(r, pr);
                }
                out[off + (size_t)d*TT] = __fsub_rn(zb[i], r);
            }
            if (more) {
                #pragma unroll
                for (int i = 0; i < 8; i++) { rb[i] = rn_[i]; zb[i] = zn_[i]; }
            }
        }
    }

    // ---- loss partial (clones contribute 0) ----
    red[tid] = active ? lacc : 0.f;
    if (tid < 256 - THREADS) red[THREADS + tid] = 0.f;
    __syncthreads();
    for (int s = 128; s > 0; s >>= 1) {
        if (tid < s) red[tid] += red[tid + s];
        __syncthreads();
    }
    if (tid == 0) g_lpart[blockIdx.x] = red[0];
}

// ---------------------------------------------------------------------------
// Deterministic loss reduce in fp64: cl == cbl (identical forward values)
// ---------------------------------------------------------------------------
__global__ void k_loss(float* __restrict__ out) {
    if (threadIdx.x != 0 || blockIdx.x != 0) return;
    double s = 0.0;
    for (int i = 0; i < NBLK; i++) s += (double)g_lpart[i];
    const float v = (float)(s / 524288.0);   // per-stage mean over B*C*T, summed
    out[OFF_CL]     = v;
    out[OFF_CL + 1] = v;
}

// ---------------------------------------------------------------------------
extern "C" void kernel_launch(void* const* d_in, const int* in_sizes, int n_in,
                              void* d_out, int out_size) {
    (void)in_sizes; (void)n_in; (void)out_size;
    const float* z     = (const float*)d_in[0];
    const float* in_v  = (const float*)d_in[1];
    const float* in_g  = (const float*)d_in[2];
    const float* in_b  = (const float*)d_in[3];
    const float* out_v = (const float*)d_in[4];
    const float* out_g = (const float*)d_in[5];
    const float* out_b = (const float*)d_in[6];
    const float* cb    = (const float*)d_in[7];
    float* out = (float*)d_out;

    cudaFuncSetAttribute(k_mega, cudaFuncAttributeMaxDynamicSharedMemorySize, SMEM_TOT);

    kp_win  <<<72, 256>>>(in_v, in_g);
    kp_wout <<<(NCB*DD + 255)/256, 256>>>(out_v, out_g);
    kp_cb   <<<(NCB*KK + 255)/256, 256>>>(cb);

    k_mega <<<NBLK, THREADS, SMEM_TOT>>>(z, in_b, out_b, cb, out);
    k_loss <<<1, 32>>>(out);
}

// round 12
// speedup vs baseline: 1.3115x; 1.0286x over previous
#include <cuda_runtime.h>
#include <cstdint>

// Problem dims
#define BB 8
#define DD 1024
#define TT 8192
#define NCB 9
#define KK 1024
#define NT (BB*TT)        // 65536 tokens
#define CN (NCB*8)        // 72
#define NP (NT/2)         // 32768 token pairs

// Output layout (float32, tuple flattened in order)
#define OFF_CODES ((size_t)BB*DD*TT)                  // 67108864
#define OFF_LAT   (OFF_CODES + (size_t)BB*NCB*TT)     // 67698688
#define OFF_CL    (OFF_LAT + (size_t)BB*CN*TT)        // 72417280

#define THREADS 128
#define NBLK 256          // 256*128 = 32768 = NP exactly

// Dynamic smem OVERLAY: streaming tables vs argmin tables, phase-disjoint.
// Streaming: win[8192] wo[8192] ob[1024] = 17408 f
// Argmin:    cb2[8192] cc2[1024]          =  9216 f (overlays win + wo head)
#define SM_WIN 0          // 8192 f : win [d][8] plain
#define SM_WO  8192       // 8192 f : wout (stage n-1) [d][8] plain
#define SM_OB  16384      // 1024 f
#define SM_CB2 0          // 8192 f : codebook pair-interleaved (overlay)
#define SM_CC2 8192       // 1024 f : (overlay)
#define SMEM_TOT (17408*4)   // 69632 bytes -> up to 3 blocks/SM

// Scratch (__device__ globals: allowed; no runtime allocation)
__device__ float g_resA[(size_t)BB*DD*TT];           // res1, res3, res5, res7 (odd stages)
__device__ float g_resB[(size_t)BB*DD*TT];           // res2, res4, res6, res8 (even stages)
__device__ __align__(16) float g_WinT[NCB*DD*8];     // [n][d][c]
__device__ __align__(16) float g_WoutT[NCB*DD*8];    // [n][d][c]
__device__ __align__(16) float g_cbn[NCB*KK*8];      // normalized codebook (ref fp32 semantics)
__device__ __align__(16) float g_cc[NCB*KK];         // sum(c_n*c_n)
__device__ __align__(16) float g_lpart[NBLK];

// ---------------------------------------------------------------------------
// f32x2 packed helpers (each lane an exact IEEE fp32 op)
// ---------------------------------------------------------------------------
__device__ __forceinline__ unsigned long long pk2(float lo, float hi) {
    unsigned long long r;
    asm("mov.b64 %0, {%1, %2};" : "=l"(r) : "f"(lo), "f"(hi));
    return r;
}
__device__ __forceinline__ void upk2(unsigned long long v, float& lo, float& hi) {
    asm("mov.b64 {%0, %1}, %2;" : "=f"(lo), "=f"(hi) : "l"(v));
}
__device__ __forceinline__ unsigned long long ffma2(unsigned long long a, unsigned long long b, unsigned long long c) {
    unsigned long long r;
    asm("fma.rn.f32x2 %0, %1, %2, %3;" : "=l"(r) : "l"(a), "l"(b), "l"(c));
    return r;
}
__device__ __forceinline__ unsigned long long fmul2(unsigned long long a, unsigned long long b) {
    unsigned long long r;
    asm("mul.rn.f32x2 %0, %1, %2;" : "=l"(r) : "l"(a), "l"(b));
    return r;
}
__device__ __forceinline__ unsigned long long fadd2(unsigned long long a, unsigned long long b) {
    unsigned long long r;
    asm("add.rn.f32x2 %0, %1, %2;" : "=l"(r) : "l"(a), "l"(b));
    return r;
}
#define SGN2 0x8000000080000000ull

// ---------------------------------------------------------------------------
// Prep: weight-norm input rows (fp64 norms), store [n][d][8c]
// ---------------------------------------------------------------------------
__global__ void kp_win(const float* __restrict__ in_v, const float* __restrict__ in_g) {
    const int row = blockIdx.x;               // 0..71 = n*8 + c
    const int n = row >> 3, c = row & 7;
    const float* src = in_v + (size_t)row * DD;
    __shared__ double red[256];
    double ss = 0.0;
    for (int d = threadIdx.x; d < DD; d += 256) { double v = src[d]; ss += v*v; }
    red[threadIdx.x] = ss; __syncthreads();
    for (int s = 128; s > 0; s >>= 1) {
        if (threadIdx.x < s) red[threadIdx.x] += red[threadIdx.x + s];
        __syncthreads();
    }
    const float scale = (float)((double)in_g[row] / sqrt(red[0]));
    for (int d = threadIdx.x; d < DD; d += 256)
        g_WinT[(size_t)n*DD*8 + d*8 + c] = src[d] * scale;
}

// ---------------------------------------------------------------------------
// Prep: weight-norm output rows (norm over C=8, fp64), store [n][d][8c]
// ---------------------------------------------------------------------------
__global__ void kp_wout(const float* __restrict__ out_v, const float* __restrict__ out_g) {
    const int i = blockIdx.x * 256 + threadIdx.x;   // (n, d)
    if (i >= NCB*DD) return;
    const int n = i / DD, d = i - n*DD;
    const float* v = out_v + (size_t)i * 8;
    double ss = 0.0;
    #pragma unroll
    for (int c = 0; c < 8; c++) { double x = v[c]; ss += x*x; }
    const float sc = (float)((double)out_g[i] / sqrt(ss));
    #pragma unroll
    for (int c = 0; c < 8; c++) g_WoutT[(size_t)n*DD*8 + d*8 + c] = v[c] * sc;
}

// ---------------------------------------------------------------------------
// Prep: normalized codebook + cc = sum(c_n^2), replicating fp32 elementwise ops
// ---------------------------------------------------------------------------
__global__ void kp_cb(const float* __restrict__ cb) {
    const int r = blockIdx.x * 256 + threadIdx.x;   // (n, k)
    if (r >= NCB*KK) return;
    const float* v = cb + (size_t)r * 8;
    float ss = 0.f;
    #pragma unroll
    for (int c = 0; c < 8; c++) ss = __fadd_rn(ss, __fmul_rn(v[c], v[c]));
    const float nr = fmaxf(__fsqrt_rn(ss), 1e-12f);
    float cn[8];
    #pragma unroll
    for (int c = 0; c < 8; c++) cn[c] = __fdiv_rn(v[c], nr);
    #pragma unroll
    for (int c = 0; c < 8; c++) g_cbn[(size_t)r*8 + c] = cn[c];
    float s2 = 0.f;
    #pragma unroll
    for (int c = 0; c < 8; c++) s2 = __fadd_rn(s2, __fmul_rn(cn[c], cn[c]));
    g_cc[r] = s2;
}

// ---------------------------------------------------------------------------
// Mega kernel: one thread owns TWO adjacent tokens (lanes of f32x2) through all
// 9 stages + final pass. Per-lane op sequences bit-identical to R11/R9 passing
// kernels. Every-stage residual checkpointing (writes each stage, single
// projection per stage). Plain smem tables with pk2-at-use; smem overlay
// (streaming vs argmin tables) keeps the footprint at 68KB.
// ---------------------------------------------------------------------------
__global__ void __launch_bounds__(THREADS, 3) k_mega(const float* __restrict__ z,
                                                     const float* __restrict__ in_b,
                                                     const float* __restrict__ out_b,
                                                     const float* __restrict__ cb_raw,
                                                     float* __restrict__ out) {
    extern __shared__ float smf[];
    __shared__ float red[THREADS];

    const int tid = threadIdx.x;
    const int p = blockIdx.x * THREADS + tid;    // 0..32767, exact
    const int token = 2 * p;
    const int b = token >> 13;
    const int t = token & (TT - 1);
    const size_t off = (size_t)b*DD*TT + t;

    float zqA0[8] = {0,0,0,0,0,0,0,0}, zqA1[8] = {0,0,0,0,0,0,0,0};
    float lacc = 0.f;

    for (int n = 0; n < NCB; n++) {
        // stage m>=1 writes: A if m odd, B if m even. stage n reads stage n-1's buffer.
        const float* rin = (n <= 1) ? z
                         : (((n & 1) == 0) ? (const float*)g_resA : (const float*)g_resB);
        float* wr = (n == 0) ? nullptr : ((n & 1) ? g_resA : g_resB);

        // ---- load STREAMING tables into overlay ----
        __syncthreads();   // prev stage argmin done with smem
        for (int i = tid; i < DD*8; i += THREADS) smf[SM_WIN + i] = g_WinT[(size_t)n*DD*8 + i];
        if (n >= 1) {
            for (int i = tid; i < DD*8; i += THREADS)
                smf[SM_WO + i] = g_WoutT[(size_t)(n-1)*DD*8 + i];
            for (int i = tid; i < DD; i += THREADS)
                smf[SM_OB + i] = out_b[(n-1)*DD + i];
        }
        __syncthreads();

        unsigned long long zq2[8];
        #pragma unroll
        for (int c = 0; c < 8; c++) zq2[c] = pk2(zqA0[c], zqA1[c]);

        // ---- Phase 1: stream residual pair (depth-16 u64), proj, z_e ----
        unsigned long long acc[8] = {0,0,0,0,0,0,0,0};
        unsigned long long rbuf[16];
        #pragma unroll
        for (int i = 0; i < 16; i++)
            rbuf[i] = *(const unsigned long long*)(rin + off + (size_t)i*TT);

        for (int d0 = 0; d0 < DD; d0 += 16) {
            unsigned long long rnx[16];
            const bool more = (d0 + 16) < DD;
            if (more) {
                #pragma unroll
                for (int i = 0; i < 16; i++)
                    rnx[i] = *(const unsigned long long*)(rin + off + (size_t)(d0 + 16 + i)*TT);
            }
            #pragma unroll
            for (int i = 0; i < 16; i++) {
                const int d = d0 + i;
                unsigned long long r2 = rbuf[i];
                if (n >= 1) {
                    const float4 wa = *(const float4*)&smf[SM_WO + d*8];
                    const float4 wb = *(const float4*)&smf[SM_WO + d*8 + 4];
                    unsigned long long dt = ffma2(pk2(wa.x, wa.x), zq2[0], 0ull);
                    dt = ffma2(pk2(wa.y, wa.y), zq2[1], dt);
                    dt = ffma2(pk2(wa.z, wa.z), zq2[2], dt);
                    dt = ffma2(pk2(wa.w, wa.w), zq2[3], dt);
                    dt = ffma2(pk2(wb.x, wb.x), zq2[4], dt);
                    dt = ffma2(pk2(wb.y, wb.y), zq2[5], dt);
                    dt = ffma2(pk2(wb.z, wb.z), zq2[6], dt);
                    dt = ffma2(pk2(wb.w, wb.w), zq2[7], dt);
                    const float obv = smf[SM_OB + d];
                    const unsigned long long pr = fadd2(dt, pk2(obv, obv));  // dot + ob
                    r2 = fadd2(r2, pr ^ SGN2);                                // rn(r - pr)
                    *(unsigned long long*)(wr + off + (size_t)d*TT) = r2;
                }
                const float4 na = *(const float4*)&smf[SM_WIN + d*8];
                const float4 nb = *(const float4*)&smf[SM_WIN + d*8 + 4];
                acc[0] = ffma2(pk2(na.x, na.x), r2, acc[0]);
                acc[1] = ffma2(pk2(na.y, na.y), r2, acc[1]);
                acc[2] = ffma2(pk2(na.z, na.z), r2, acc[2]);
                acc[3] = ffma2(pk2(na.w, na.w), r2, acc[3]);
                acc[4] = ffma2(pk2(nb.x, nb.x), r2, acc[4]);
                acc[5] = ffma2(pk2(nb.y, nb.y), r2, acc[5]);
                acc[6] = ffma2(pk2(nb.z, nb.z), r2, acc[6]);
                acc[7] = ffma2(pk2(nb.w, nb.w), r2, acc[7]);
            }
            if (more) {
                #pragma unroll
                for (int i = 0; i < 16; i++) rbuf[i] = rnx[i];
            }
        }

        // ---- swap overlay: load ARGMIN tables ----
        __syncthreads();   // streaming done with win/wo/ob
        for (int i = tid; i < KK*8; i += THREADS) {
            const int k = i >> 3, c = i & 7;
            smf[SM_CB2 + (k >> 1)*16 + c*2 + (k & 1)] = g_cbn[(size_t)n*KK*8 + i];
        }
        for (int k = tid; k < KK; k += THREADS) smf[SM_CC2 + k] = g_cc[n*KK + k];
        __syncthreads();

        // ---- Phase 2: z_e per token, normalize (identical scalar ops) ----
        float e0[8], e1[8];
        #pragma unroll
        for (int c = 0; c < 8; c++) {
            upk2(acc[c], e0[c], e1[c]);
            const float vb = __ldg(in_b + n*8 + c);
            e0[c] = __fadd_rn(e0[c], vb);
            e1[c] = __fadd_rn(e1[c], vb);
        }

        unsigned long long enA[8], enB[8], eepA, eepB;
        {
            float ssq = 0.f;
            #pragma unroll
            for (int c = 0; c < 8; c++) ssq = __fadd_rn(ssq, __fmul_rn(e0[c], e0[c]));
            const float rho = fmaxf(__fsqrt_rn(ssq), 1e-12f);
            float en[8], ee = 0.f;
            #pragma unroll
            for (int c = 0; c < 8; c++) en[c] = __fdiv_rn(e0[c], rho);
            #pragma unroll
            for (int c = 0; c < 8; c++) ee = __fadd_rn(ee, __fmul_rn(en[c], en[c]));
            #pragma unroll
            for (int c = 0; c < 8; c++) enA[c] = pk2(en[c], en[c]);
            eepA = pk2(ee, ee);
        }
        {
            float ssq = 0.f;
            #pragma unroll
            for (int c = 0; c < 8; c++) ssq = __fadd_rn(ssq, __fmul_rn(e1[c], e1[c]));
            const float rho = fmaxf(__fsqrt_rn(ssq), 1e-12f);
            float en[8], ee = 0.f;
            #pragma unroll
            for (int c = 0; c < 8; c++) en[c] = __fdiv_rn(e1[c], rho);
            #pragma unroll
            for (int c = 0; c < 8; c++) ee = __fadd_rn(ee, __fmul_rn(en[c], en[c]));
            #pragma unroll
            for (int c = 0; c < 8; c++) enB[c] = pk2(en[c], en[c]);
            eepB = pk2(ee, ee);
        }
        const unsigned long long m2 = pk2(-2.f, -2.f);

        // ---- argmin: both tokens share codebook LDS; per-token 4-chain
        //      first-wins logic identical to R9/R10 passing kernels ----
        float aA = 3.4e38f, aB = 3.4e38f, aC = 3.4e38f, aD = 3.4e38f;
        int   jA = 0, jB = 0, jC = 0, jD = 0;
        float bA_ = 3.4e38f, bB_ = 3.4e38f, bC_ = 3.4e38f, bD_ = 3.4e38f;
        int   kA = 0, kB = 0, kC = 0, kD = 0;
        const unsigned long long* cbu = (const unsigned long long*)&smf[SM_CB2];
        const unsigned long long* ccu = (const unsigned long long*)&smf[SM_CC2];
        for (int k2 = 0; k2 < KK/2; k2 += 2) {
            const ulonglong2 ca0 = *(const ulonglong2*)(cbu + k2*8);
            const ulonglong2 cb0 = *(const ulonglong2*)(cbu + k2*8 + 2);
            const ulonglong2 cc0 = *(const ulonglong2*)(cbu + k2*8 + 4);
            const ulonglong2 cd0 = *(const ulonglong2*)(cbu + k2*8 + 6);
            const ulonglong2 ca1 = *(const ulonglong2*)(cbu + (k2+1)*8);
            const ulonglong2 cb1 = *(const ulonglong2*)(cbu + (k2+1)*8 + 2);
            const ulonglong2 cc1 = *(const ulonglong2*)(cbu + (k2+1)*8 + 4);
            const ulonglong2 cd1 = *(const ulonglong2*)(cbu + (k2+1)*8 + 6);
            const unsigned long long ccv0 = ccu[k2], ccv1 = ccu[k2+1];
            {
                unsigned long long dp0 = fmul2(enA[0], ca0.x);
                unsigned long long dp1 = fmul2(enA[0], ca1.x);
                dp0 = ffma2(enA[1], ca0.y, dp0);  dp1 = ffma2(enA[1], ca1.y, dp1);
                dp0 = ffma2(enA[2], cb0.x, dp0);  dp1 = ffma2(enA[2], cb1.x, dp1);
                dp0 = ffma2(enA[3], cb0.y, dp0);  dp1 = ffma2(enA[3], cb1.y, dp1);
                dp0 = ffma2(enA[4], cc0.x, dp0);  dp1 = ffma2(enA[4], cc1.x, dp1);
                dp0 = ffma2(enA[5], cc0.y, dp0);  dp1 = ffma2(enA[5], cc1.y, dp1);
                dp0 = ffma2(enA[6], cd0.x, dp0);  dp1 = ffma2(enA[6], cd1.x, dp1);
                dp0 = ffma2(enA[7], cd0.y, dp0);  dp1 = ffma2(enA[7], cd1.y, dp1);
                const unsigned long long t0 = ffma2(m2, dp0, eepA);
                const unsigned long long t1 = ffma2(m2, dp1, eepA);
                const unsigned long long di0 = fadd2(t0, ccv0);
                const unsigned long long di1 = fadd2(t1, ccv1);
                float d0v, d1v, d2v, d3v;
                upk2(di0, d0v, d1v); upk2(di1, d2v, d3v);
                if (d0v < aA) { aA = d0v; jA = 2*k2; }
                if (d1v < aB) { aB = d1v; jB = 2*k2 + 1; }
                if (d2v < aC) { aC = d2v; jC = 2*k2 + 2; }
                if (d3v < aD) { aD = d3v; jD = 2*k2 + 3; }
            }
            {
                unsigned long long dp0 = fmul2(enB[0], ca0.x);
                unsigned long long dp1 = fmul2(enB[0], ca1.x);
                dp0 = ffma2(enB[1], ca0.y, dp0);  dp1 = ffma2(enB[1], ca1.y, dp1);
                dp0 = ffma2(enB[2], cb0.x, dp0);  dp1 = ffma2(enB[2], cb1.x, dp1);
                dp0 = ffma2(enB[3], cb0.y, dp0);  dp1 = ffma2(enB[3], cb1.y, dp1);
                dp0 = ffma2(enB[4], cc0.x, dp0);  dp1 = ffma2(enB[4], cc1.x, dp1);
                dp0 = ffma2(enB[5], cc0.y, dp0);  dp1 = ffma2(enB[5], cc1.y, dp1);
                dp0 = ffma2(enB[6], cd0.x, dp0);  dp1 = ffma2(enB[6], cd1.x, dp1);
                dp0 = ffma2(enB[7], cd0.y, dp0);  dp1 = ffma2(enB[7], cd1.y, dp1);
                const unsigned long long t0 = ffma2(m2, dp0, eepB);
                const unsigned long long t1 = ffma2(m2, dp1, eepB);
                const unsigned long long di0 = fadd2(t0, ccv0);
                const unsigned long long di1 = fadd2(t1, ccv1);
                float d0v, d1v, d2v, d3v;
                upk2(di0, d0v, d1v); upk2(di1, d2v, d3v);
                if (d0v < bA_) { bA_ = d0v; kA = 2*k2; }
                if (d1v < bB_) { bB_ = d1v; kB = 2*k2 + 1; }
                if (d2v < bC_) { bC_ = d2v; kC = 2*k2 + 2; }
                if (d3v < bD_) { bD_ = d3v; kD = 2*k2 + 3; }
            }
        }
        float best0 = aA; int bi0 = jA;
        if (aB < best0 || (aB == best0 && jB < bi0)) { best0 = aB; bi0 = jB; }
        if (aC < best0 || (aC == best0 && jC < bi0)) { best0 = aC; bi0 = jC; }
        if (aD < best0 || (aD == best0 && jD < bi0)) { best0 = aD; bi0 = jD; }
        float best1 = bA_; int bi1 = kA;
        if (bB_ < best1 || (bB_ == best1 && kB < bi1)) { best1 = bB_; bi1 = kB; }
        if (bC_ < best1 || (bC_ == best1 && kC < bi1)) { best1 = bC_; bi1 = kC; }
        if (bD_ < best1 || (bD_ == best1 && kD < bi1)) { best1 = bD_; bi1 = kD; }

        // ---- Phase 3: winners, straight-through, outputs ----
        const float* q0p = cb_raw + ((size_t)n*KK + bi0)*8;
        const float* q1p = cb_raw + ((size_t)n*KK + bi1)*8;
        const float4 qa0 = __ldg((const float4*)q0p);
        const float4 qa1 = __ldg((const float4*)(q0p + 4));
        const float4 qb0 = __ldg((const float4*)q1p);
        const float4 qb1 = __ldg((const float4*)(q1p + 4));
        const float q0[8] = {qa0.x, qa0.y, qa0.z, qa0.w, qa1.x, qa1.y, qa1.z, qa1.w};
        const float q1[8] = {qb0.x, qb0.y, qb0.z, qb0.w, qb1.x, qb1.y, qb1.z, qb1.w};

        #pragma unroll
        for (int c = 0; c < 8; c++) {
            const float dl0 = __fsub_rn(e0[c], q0[c]);
            lacc = fmaf(dl0, dl0, lacc);
            const float dl1 = __fsub_rn(e1[c], q1[c]);
            lacc = fmaf(dl1, dl1, lacc);
            zqA0[c] = __fadd_rn(e0[c], __fsub_rn(q0[c], e0[c]));
            zqA1[c] = __fadd_rn(e1[c], __fsub_rn(q1[c], e1[c]));
        }

        *(float2*)&out[OFF_CODES + (size_t)b*NCB*TT + (size_t)n*TT + t] =
            make_float2((float)bi0, (float)bi1);
        #pragma unroll
        for (int c = 0; c < 8; c++)
            *(float2*)&out[OFF_LAT + (size_t)b*CN*TT + (size_t)(n*8 + c)*TT + t] =
                make_float2(e0[c], e1[c]);
    }

    // ---- Final pass: res8(B) -> proj8 (zqA) -> out = z - res9 ----
    __syncthreads();
    for (int i = tid; i < DD*8; i += THREADS)
        smf[SM_WO + i] = g_WoutT[(size_t)8*DD*8 + i];
    for (int i = tid; i < DD; i += THREADS)
        smf[SM_OB + i] = out_b[8*DD + i];
    __syncthreads();

    {
        unsigned long long zq2[8];
        #pragma unroll
        for (int c = 0; c < 8; c++) zq2[c] = pk2(zqA0[c], zqA1[c]);

        unsigned long long rb[8], zb[8];
        #pragma unroll
        for (int i = 0; i < 8; i++) {
            rb[i] = *(const unsigned long long*)((const float*)g_resB + off + (size_t)i*TT);
            zb[i] = *(const unsigned long long*)(z + off + (size_t)i*TT);
        }
        for (int d0 = 0; d0 < DD; d0 += 8) {
            unsigned long long rn_[8], zn_[8];
            const bool more = (d0 + 8) < DD;
            if (more) {
                #pragma unroll
                for (int i = 0; i < 8; i++) {
                    rn_[i] = *(const unsigned long long*)((const float*)g_resB + off + (size_t)(d0 + 8 + i)*TT);
                    zn_[i] = *(const unsigned long long*)(z + off + (size_t)(d0 + 8 + i)*TT);
                }
            }
            #pragma unroll
            for (int i = 0; i < 8; i++) {
                const int d = d0 + i;
                const float4 wa = *(const float4*)&smf[SM_WO + d*8];
                const float4 wb = *(const float4*)&smf[SM_WO + d*8 + 4];
                unsigned long long dt = ffma2(pk2(wa.x, wa.x), zq2[0], 0ull);
                dt = ffma2(pk2(wa.y, wa.y), zq2[1], dt);
                dt = ffma2(pk2(wa.z, wa.z), zq2[2], dt);
                dt = ffma2(pk2(wa.w, wa.w), zq2[3], dt);
                dt = ffma2(pk2(wb.x, wb.x), zq2[4], dt);
                dt = ffma2(pk2(wb.y, wb.y), zq2[5], dt);
                dt = ffma2(pk2(wb.z, wb.z), zq2[6], dt);
                dt = ffma2(pk2(wb.w, wb.w), zq2[7], dt);
                const float obv = smf[SM_OB + d];
                const unsigned long long pr = fadd2(dt, pk2(obv, obv));
                const unsigned long long r9 = fadd2(rb[i], pr ^ SGN2);   // rn(r8 - pr)
                *(unsigned long long*)&out[off + (size_t)d*TT] = fadd2(zb[i], r9 ^ SGN2); // rn(z - r9)
            }
            if (more) {
                #pragma unroll
                for (int i = 0; i < 8; i++) { rb[i] = rn_[i]; zb[i] = zn_[i]; }
            }
        }
    }

    // ---- loss partial ----
    red[tid] = lacc; __syncthreads();
    for (int s = THREADS/2; s > 0; s >>= 1) {
        if (tid < s) red[tid] += red[tid + s];
        __syncthreads();
    }
    if (tid == 0) g_lpart[blockIdx.x] = red[0];
}

// ---------------------------------------------------------------------------
// Deterministic loss reduce in fp64: cl == cbl (identical forward values)
// ---------------------------------------------------------------------------
__global__ void k_loss(float* __restrict__ out) {
    if (threadIdx.x != 0 || blockIdx.x != 0) return;
    double s = 0.0;
    for (int i = 0; i < NBLK; i++) s += (double)g_lpart[i];
    const float v = (float)(s / 524288.0);   // per-stage mean over B*C*T, summed
    out[OFF_CL]     = v;
    out[OFF_CL + 1] = v;
}

// ---------------------------------------------------------------------------
extern "C" void kernel_launch(void* const* d_in, const int* in_sizes, int n_in,
                              void* d_out, int out_size) {
    (void)in_sizes; (void)n_in; (void)out_size;
    const float* z     = (const float*)d_in[0];
    const float* in_v  = (const float*)d_in[1];
    const float* in_g  = (const float*)d_in[2];
    const float* in_b  = (const float*)d_in[3];
    const float* out_v = (const float*)d_in[4];
    const float* out_g = (const float*)d_in[5];
    const float* out_b = (const float*)d_in[6];
    const float* cb    = (const float*)d_in[7];
    float* out = (float*)d_out;

    cudaFuncSetAttribute(k_mega, cudaFuncAttributeMaxDynamicSharedMemorySize, SMEM_TOT);

    kp_win  <<<72, 256>>>(in_v, in_g);
    kp_wout <<<(NCB*DD + 255)/256, 256>>>(out_v, out_g);
    kp_cb   <<<(NCB*KK + 255)/256, 256>>>(cb);

    k_mega <<<NBLK, THREADS, SMEM_TOT>>>(z, in_b, out_b, cb, out);
    k_loss <<<1, 32>>>(out);
}

// round 13
// speedup vs baseline: 1.4413x; 1.0989x over previous
#include <cuda_runtime.h>
#include <cstdint>

// Problem dims
#define BB 8
#define DD 1024
#define TT 8192
#define NCB 9
#define KK 1024
#define NT (BB*TT)        // 65536 tokens
#define CN (NCB*8)        // 72
#define NP (NT/2)         // 32768 token pairs

// Output layout (float32, tuple flattened in order)
#define OFF_CODES ((size_t)BB*DD*TT)                  // 67108864
#define OFF_LAT   (OFF_CODES + (size_t)BB*NCB*TT)     // 67698688
#define OFF_CL    (OFF_LAT + (size_t)BB*CN*TT)        // 72417280

#define THREADS 128
#define NBLK 256          // 256*128 = 32768 = NP exactly

// Dynamic smem OVERLAY: streaming tables vs argmin tables, phase-disjoint.
#define SM_WIN 0          // 8192 f : win [d][8] plain
#define SM_WO  8192       // 8192 f : wout (stage n-1) [d][8] plain
#define SM_OB  16384      // 1024 f
#define SM_CB2 0          // 8192 f : codebook pair-interleaved (overlay)
#define SM_CC2 8192       // 1024 f : (overlay)
#define SMEM_TOT (17408*4)   // 69632 bytes

// Scratch (__device__ globals: allowed; no runtime allocation)
__device__ float g_resA[(size_t)BB*DD*TT];           // res1, res3, res5, res7 (odd stages)
__device__ float g_resB[(size_t)BB*DD*TT];           // res2, res4, res6, res8 (even stages)
__device__ __align__(16) float g_WinT[NCB*DD*8];     // [n][d][c]
__device__ __align__(16) float g_WoutT[NCB*DD*8];    // [n][d][c]
__device__ __align__(16) float g_cbn[NCB*KK*8];      // normalized codebook (ref fp32 semantics)
__device__ __align__(16) float g_cc[NCB*KK];         // sum(c_n*c_n)
__device__ __align__(16) float g_lpart[NBLK];

// ---------------------------------------------------------------------------
// f32x2 packed helpers (each lane an exact IEEE fp32 op)
// ---------------------------------------------------------------------------
__device__ __forceinline__ unsigned long long pk2(float lo, float hi) {
    unsigned long long r;
    asm("mov.b64 %0, {%1, %2};" : "=l"(r) : "f"(lo), "f"(hi));
    return r;
}
__device__ __forceinline__ void upk2(unsigned long long v, float& lo, float& hi) {
    asm("mov.b64 {%0, %1}, %2;" : "=f"(lo), "=f"(hi) : "l"(v));
}
__device__ __forceinline__ unsigned long long ffma2(unsigned long long a, unsigned long long b, unsigned long long c) {
    unsigned long long r;
    asm("fma.rn.f32x2 %0, %1, %2, %3;" : "=l"(r) : "l"(a), "l"(b), "l"(c));
    return r;
}
__device__ __forceinline__ unsigned long long fmul2(unsigned long long a, unsigned long long b) {
    unsigned long long r;
    asm("mul.rn.f32x2 %0, %1, %2;" : "=l"(r) : "l"(a), "l"(b));
    return r;
}
__device__ __forceinline__ unsigned long long fadd2(unsigned long long a, unsigned long long b) {
    unsigned long long r;
    asm("add.rn.f32x2 %0, %1, %2;" : "=l"(r) : "l"(a), "l"(b));
    return r;
}
#define SGN2 0x8000000080000000ull

// ---------------------------------------------------------------------------
// Prep: weight-norm input rows (fp64 norms), store [n][d][8c]
// ---------------------------------------------------------------------------
__global__ void kp_win(const float* __restrict__ in_v, const float* __restrict__ in_g) {
    const int row = blockIdx.x;               // 0..71 = n*8 + c
    const int n = row >> 3, c = row & 7;
    const float* src = in_v + (size_t)row * DD;
    __shared__ double red[256];
    double ss = 0.0;
    for (int d = threadIdx.x; d < DD; d += 256) { double v = src[d]; ss += v*v; }
    red[threadIdx.x] = ss; __syncthreads();
    for (int s = 128; s > 0; s >>= 1) {
        if (threadIdx.x < s) red[threadIdx.x] += red[threadIdx.x + s];
        __syncthreads();
    }
    const float scale = (float)((double)in_g[row] / sqrt(red[0]));
    for (int d = threadIdx.x; d < DD; d += 256)
        g_WinT[(size_t)n*DD*8 + d*8 + c] = src[d] * scale;
}

// ---------------------------------------------------------------------------
// Prep: weight-norm output rows (norm over C=8, fp64), store [n][d][8c]
// ---------------------------------------------------------------------------
__global__ void kp_wout(const float* __restrict__ out_v, const float* __restrict__ out_g) {
    const int i = blockIdx.x * 256 + threadIdx.x;   // (n, d)
    if (i >= NCB*DD) return;
    const int n = i / DD, d = i - n*DD;
    const float* v = out_v + (size_t)i * 8;
    double ss = 0.0;
    #pragma unroll
    for (int c = 0; c < 8; c++) { double x = v[c]; ss += x*x; }
    const float sc = (float)((double)out_g[i] / sqrt(ss));
    #pragma unroll
    for (int c = 0; c < 8; c++) g_WoutT[(size_t)n*DD*8 + d*8 + c] = v[c] * sc;
}

// ---------------------------------------------------------------------------
// Prep: normalized codebook + cc = sum(c_n^2), replicating fp32 elementwise ops
// ---------------------------------------------------------------------------
__global__ void kp_cb(const float* __restrict__ cb) {
    const int r = blockIdx.x * 256 + threadIdx.x;   // (n, k)
    if (r >= NCB*KK) return;
    const float* v = cb + (size_t)r * 8;
    float ss = 0.f;
    #pragma unroll
    for (int c = 0; c < 8; c++) ss = __fadd_rn(ss, __fmul_rn(v[c], v[c]));
    const float nr = fmaxf(__fsqrt_rn(ss), 1e-12f);
    float cn[8];
    #pragma unroll
    for (int c = 0; c < 8; c++) cn[c] = __fdiv_rn(v[c], nr);
    #pragma unroll
    for (int c = 0; c < 8; c++) g_cbn[(size_t)r*8 + c] = cn[c];
    float s2 = 0.f;
    #pragma unroll
    for (int c = 0; c < 8; c++) s2 = __fadd_rn(s2, __fmul_rn(cn[c], cn[c]));
    g_cc[r] = s2;
}

// ---------------------------------------------------------------------------
// Mega kernel: identical arithmetic to R12 (passing, rel_err 6.31932e-07).
// R13 delta (load scheduling only): depth-32 u64 double-buffered prefetch in
// the stage streaming loop (256 B/thread in flight), launch_bounds(128, 2).
// ---------------------------------------------------------------------------
__global__ void __launch_bounds__(THREADS, 2) k_mega(const float* __restrict__ z,
                                                     const float* __restrict__ in_b,
                                                     const float* __restrict__ out_b,
                                                     const float* __restrict__ cb_raw,
                                                     float* __restrict__ out) {
    extern __shared__ float smf[];
    __shared__ float red[THREADS];

    const int tid = threadIdx.x;
    const int p = blockIdx.x * THREADS + tid;    // 0..32767, exact
    const int token = 2 * p;
    const int b = token >> 13;
    const int t = token & (TT - 1);
    const size_t off = (size_t)b*DD*TT + t;

    float zqA0[8] = {0,0,0,0,0,0,0,0}, zqA1[8] = {0,0,0,0,0,0,0,0};
    float lacc = 0.f;

    for (int n = 0; n < NCB; n++) {
        const float* rin = (n <= 1) ? z
                         : (((n & 1) == 0) ? (const float*)g_resA : (const float*)g_resB);
        float* wr = (n == 0) ? nullptr : ((n & 1) ? g_resA : g_resB);

        // ---- load STREAMING tables into overlay ----
        __syncthreads();   // prev stage argmin done with smem
        for (int i = tid; i < DD*8; i += THREADS) smf[SM_WIN + i] = g_WinT[(size_t)n*DD*8 + i];
        if (n >= 1) {
            for (int i = tid; i < DD*8; i += THREADS)
                smf[SM_WO + i] = g_WoutT[(size_t)(n-1)*DD*8 + i];
            for (int i = tid; i < DD; i += THREADS)
                smf[SM_OB + i] = out_b[(n-1)*DD + i];
        }
        __syncthreads();

        unsigned long long zq2[8];
        #pragma unroll
        for (int c = 0; c < 8; c++) zq2[c] = pk2(zqA0[c], zqA1[c]);

        // ---- Phase 1: stream residual pair (depth-32 u64), proj, z_e ----
        unsigned long long acc[8] = {0,0,0,0,0,0,0,0};
        unsigned long long rbuf[32];
        #pragma unroll
        for (int i = 0; i < 32; i++)
            rbuf[i] = *(const unsigned long long*)(rin + off + (size_t)i*TT);

        for (int d0 = 0; d0 < DD; d0 += 32) {
            unsigned long long rnx[32];
            const bool more = (d0 + 32) < DD;
            if (more) {
                #pragma unroll
                for (int i = 0; i < 32; i++)
                    rnx[i] = *(const unsigned long long*)(rin + off + (size_t)(d0 + 32 + i)*TT);
            }
            #pragma unroll
            for (int i = 0; i < 32; i++) {
                const int d = d0 + i;
                unsigned long long r2 = rbuf[i];
                if (n >= 1) {
                    const float4 wa = *(const float4*)&smf[SM_WO + d*8];
                    const float4 wb = *(const float4*)&smf[SM_WO + d*8 + 4];
                    unsigned long long dt = ffma2(pk2(wa.x, wa.x), zq2[0], 0ull);
                    dt = ffma2(pk2(wa.y, wa.y), zq2[1], dt);
                    dt = ffma2(pk2(wa.z, wa.z), zq2[2], dt);
                    dt = ffma2(pk2(wa.w, wa.w), zq2[3], dt);
                    dt = ffma2(pk2(wb.x, wb.x), zq2[4], dt);
                    dt = ffma2(pk2(wb.y, wb.y), zq2[5], dt);
                    dt = ffma2(pk2(wb.z, wb.z), zq2[6], dt);
                    dt = ffma2(pk2(wb.w, wb.w), zq2[7], dt);
                    const float obv = smf[SM_OB + d];
                    const unsigned long long pr = fadd2(dt, pk2(obv, obv));  // dot + ob
                    r2 = fadd2(r2, pr ^ SGN2);                                // rn(r - pr)
                    *(unsigned long long*)(wr + off + (size_t)d*TT) = r2;
                }
                const float4 na = *(const float4*)&smf[SM_WIN + d*8];
                const float4 nb = *(const float4*)&smf[SM_WIN + d*8 + 4];
                acc[0] = ffma2(pk2(na.x, na.x), r2, acc[0]);
                acc[1] = ffma2(pk2(na.y, na.y), r2, acc[1]);
                acc[2] = ffma2(pk2(na.z, na.z), r2, acc[2]);
                acc[3] = ffma2(pk2(na.w, na.w), r2, acc[3]);
                acc[4] = ffma2(pk2(nb.x, nb.x), r2, acc[4]);
                acc[5] = ffma2(pk2(nb.y, nb.y), r2, acc[5]);
                acc[6] = ffma2(pk2(nb.z, nb.z), r2, acc[6]);
                acc[7] = ffma2(pk2(nb.w, nb.w), r2, acc[7]);
            }
            if (more) {
                #pragma unroll
                for (int i = 0; i < 32; i++) rbuf[i] = rnx[i];
            }
        }

        // ---- swap overlay: load ARGMIN tables ----
        __syncthreads();   // streaming done with win/wo/ob
        for (int i = tid; i < KK*8; i += THREADS) {
            const int k = i >> 3, c = i & 7;
            smf[SM_CB2 + (k >> 1)*16 + c*2 + (k & 1)] = g_cbn[(size_t)n*KK*8 + i];
        }
        for (int k = tid; k < KK; k += THREADS) smf[SM_CC2 + k] = g_cc[n*KK + k];
        __syncthreads();

        // ---- Phase 2: z_e per token, normalize (identical scalar ops) ----
        float e0[8], e1[8];
        #pragma unroll
        for (int c = 0; c < 8; c++) {
            upk2(acc[c], e0[c], e1[c]);
            const float vb = __ldg(in_b + n*8 + c);
            e0[c] = __fadd_rn(e0[c], vb);
            e1[c] = __fadd_rn(e1[c], vb);
        }

        unsigned long long enA[8], enB[8], eepA, eepB;
        {
            float ssq = 0.f;
            #pragma unroll
            for (int c = 0; c < 8; c++) ssq = __fadd_rn(ssq, __fmul_rn(e0[c], e0[c]));
            const float rho = fmaxf(__fsqrt_rn(ssq), 1e-12f);
            float en[8], ee = 0.f;
            #pragma unroll
            for (int c = 0; c < 8; c++) en[c] = __fdiv_rn(e0[c], rho);
            #pragma unroll
            for (int c = 0; c < 8; c++) ee = __fadd_rn(ee, __fmul_rn(en[c], en[c]));
            #pragma unroll
            for (int c = 0; c < 8; c++) enA[c] = pk2(en[c], en[c]);
            eepA = pk2(ee, ee);
        }
        {
            float ssq = 0.f;
            #pragma unroll
            for (int c = 0; c < 8; c++) ssq = __fadd_rn(ssq, __fmul_rn(e1[c], e1[c]));
            const float rho = fmaxf(__fsqrt_rn(ssq), 1e-12f);
            float en[8], ee = 0.f;
            #pragma unroll
            for (int c = 0; c < 8; c++) en[c] = __fdiv_rn(e1[c], rho);
            #pragma unroll
            for (int c = 0; c < 8; c++) ee = __fadd_rn(ee, __fmul_rn(en[c], en[c]));
            #pragma unroll
            for (int c = 0; c < 8; c++) enB[c] = pk2(en[c], en[c]);
            eepB = pk2(ee, ee);
        }
        const unsigned long long m2 = pk2(-2.f, -2.f);

        // ---- argmin: both tokens share codebook LDS; per-token 4-chain
        //      first-wins logic identical to R9/R10/R12 passing kernels ----
        float aA = 3.4e38f, aB = 3.4e38f, aC = 3.4e38f, aD = 3.4e38f;
        int   jA = 0, jB = 0, jC = 0, jD = 0;
        float bA_ = 3.4e38f, bB_ = 3.4e38f, bC_ = 3.4e38f, bD_ = 3.4e38f;
        int   kA = 0, kB = 0, kC = 0, kD = 0;
        const unsigned long long* cbu = (const unsigned long long*)&smf[SM_CB2];
        const unsigned long long* ccu = (const unsigned long long*)&smf[SM_CC2];
        for (int k2 = 0; k2 < KK/2; k2 += 2) {
            const ulonglong2 ca0 = *(const ulonglong2*)(cbu + k2*8);
            const ulonglong2 cb0 = *(const ulonglong2*)(cbu + k2*8 + 2);
            const ulonglong2 cc0 = *(const ulonglong2*)(cbu + k2*8 + 4);
            const ulonglong2 cd0 = *(const ulonglong2*)(cbu + k2*8 + 6);
            const ulonglong2 ca1 = *(const ulonglong2*)(cbu + (k2+1)*8);
            const ulonglong2 cb1 = *(const ulonglong2*)(cbu + (k2+1)*8 + 2);
            const ulonglong2 cc1 = *(const ulonglong2*)(cbu + (k2+1)*8 + 4);
            const ulonglong2 cd1 = *(const ulonglong2*)(cbu + (k2+1)*8 + 6);
            const unsigned long long ccv0 = ccu[k2], ccv1 = ccu[k2+1];
            {
                unsigned long long dp0 = fmul2(enA[0], ca0.x);
                unsigned long long dp1 = fmul2(enA[0], ca1.x);
                dp0 = ffma2(enA[1], ca0.y, dp0);  dp1 = ffma2(enA[1], ca1.y, dp1);
                dp0 = ffma2(enA[2], cb0.x, dp0);  dp1 = ffma2(enA[2], cb1.x, dp1);
                dp0 = ffma2(enA[3], cb0.y, dp0);  dp1 = ffma2(enA[3], cb1.y, dp1);
                dp0 = ffma2(enA[4], cc0.x, dp0);  dp1 = ffma2(enA[4], cc1.x, dp1);
                dp0 = ffma2(enA[5], cc0.y, dp0);  dp1 = ffma2(enA[5], cc1.y, dp1);
                dp0 = ffma2(enA[6], cd0.x, dp0);  dp1 = ffma2(enA[6], cd1.x, dp1);
                dp0 = ffma2(enA[7], cd0.y, dp0);  dp1 = ffma2(enA[7], cd1.y, dp1);
                const unsigned long long t0 = ffma2(m2, dp0, eepA);
                const unsigned long long t1 = ffma2(m2, dp1, eepA);
                const unsigned long long di0 = fadd2(t0, ccv0);
                const unsigned long long di1 = fadd2(t1, ccv1);
                float d0v, d1v, d2v, d3v;
                upk2(di0, d0v, d1v); upk2(di1, d2v, d3v);
                if (d0v < aA) { aA = d0v; jA = 2*k2; }
                if (d1v < aB) { aB = d1v; jB = 2*k2 + 1; }
                if (d2v < aC) { aC = d2v; jC = 2*k2 + 2; }
                if (d3v < aD) { aD = d3v; jD = 2*k2 + 3; }
            }
            {
                unsigned long long dp0 = fmul2(enB[0], ca0.x);
                unsigned long long dp1 = fmul2(enB[0], ca1.x);
                dp0 = ffma2(enB[1], ca0.y, dp0);  dp1 = ffma2(enB[1], ca1.y, dp1);
                dp0 = ffma2(enB[2], cb0.x, dp0);  dp1 = ffma2(enB[2], cb1.x, dp1);
                dp0 = ffma2(enB[3], cb0.y, dp0);  dp1 = ffma2(enB[3], cb1.y, dp1);
                dp0 = ffma2(enB[4], cc0.x, dp0);  dp1 = ffma2(enB[4], cc1.x, dp1);
                dp0 = ffma2(enB[5], cc0.y, dp0);  dp1 = ffma2(enB[5], cc1.y, dp1);
                dp0 = ffma2(enB[6], cd0.x, dp0);  dp1 = ffma2(enB[6], cd1.x, dp1);
                dp0 = ffma2(enB[7], cd0.y, dp0);  dp1 = ffma2(enB[7], cd1.y, dp1);
                const unsigned long long t0 = ffma2(m2, dp0, eepB);
                const unsigned long long t1 = ffma2(m2, dp1, eepB);
                const unsigned long long di0 = fadd2(t0, ccv0);
                const unsigned long long di1 = fadd2(t1, ccv1);
                float d0v, d1v, d2v, d3v;
                upk2(di0, d0v, d1v); upk2(di1, d2v, d3v);
                if (d0v < bA_) { bA_ = d0v; kA = 2*k2; }
                if (d1v < bB_) { bB_ = d1v; kB = 2*k2 + 1; }
                if (d2v < bC_) { bC_ = d2v; kC = 2*k2 + 2; }
                if (d3v < bD_) { bD_ = d3v; kD = 2*k2 + 3; }
            }
        }
        float best0 = aA; int bi0 = jA;
        if (aB < best0 || (aB == best0 && jB < bi0)) { best0 = aB; bi0 = jB; }
        if (aC < best0 || (aC == best0 && jC < bi0)) { best0 = aC; bi0 = jC; }
        if (aD < best0 || (aD == best0 && jD < bi0)) { best0 = aD; bi0 = jD; }
        float best1 = bA_; int bi1 = kA;
        if (bB_ < best1 || (bB_ == best1 && kB < bi1)) { best1 = bB_; bi1 = kB; }
        if (bC_ < best1 || (bC_ == best1 && kC < bi1)) { best1 = bC_; bi1 = kC; }
        if (bD_ < best1 || (bD_ == best1 && kD < bi1)) { best1 = bD_; bi1 = kD; }

        // ---- Phase 3: winners, straight-through, outputs ----
        const float* q0p = cb_raw + ((size_t)n*KK + bi0)*8;
        const float* q1p = cb_raw + ((size_t)n*KK + bi1)*8;
        const float4 qa0 = __ldg((const float4*)q0p);
        const float4 qa1 = __ldg((const float4*)(q0p + 4));
        const float4 qb0 = __ldg((const float4*)q1p);
        const float4 qb1 = __ldg((const float4*)(q1p + 4));
        const float q0[8] = {qa0.x, qa0.y, qa0.z, qa0.w, qa1.x, qa1.y, qa1.z, qa1.w};
        const float q1[8] = {qb0.x, qb0.y, qb0.z, qb0.w, qb1.x, qb1.y, qb1.z, qb1.w};

        #pragma unroll
        for (int c = 0; c < 8; c++) {
            const float dl0 = __fsub_rn(e0[c], q0[c]);
            lacc = fmaf(dl0, dl0, lacc);
            const float dl1 = __fsub_rn(e1[c], q1[c]);
            lacc = fmaf(dl1, dl1, lacc);
            zqA0[c] = __fadd_rn(e0[c], __fsub_rn(q0[c], e0[c]));
            zqA1[c] = __fadd_rn(e1[c], __fsub_rn(q1[c], e1[c]));
        }

        *(float2*)&out[OFF_CODES + (size_t)b*NCB*TT + (size_t)n*TT + t] =
            make_float2((float)bi0, (float)bi1);
        #pragma unroll
        for (int c = 0; c < 8; c++)
            *(float2*)&out[OFF_LAT + (size_t)b*CN*TT + (size_t)(n*8 + c)*TT + t] =
                make_float2(e0[c], e1[c]);
    }

    // ---- Final pass: res8(B) -> proj8 (zqA) -> out = z - res9 ----
    __syncthreads();
    for (int i = tid; i < DD*8; i += THREADS)
        smf[SM_WO + i] = g_WoutT[(size_t)8*DD*8 + i];
    for (int i = tid; i < DD; i += THREADS)
        smf[SM_OB + i] = out_b[8*DD + i];
    __syncthreads();

    {
        unsigned long long zq2[8];
        #pragma unroll
        for (int c = 0; c < 8; c++) zq2[c] = pk2(zqA0[c], zqA1[c]);

        unsigned long long rb[8], zb[8];
        #pragma unroll
        for (int i = 0; i < 8; i++) {
            rb[i] = *(const unsigned long long*)((const float*)g_resB + off + (size_t)i*TT);
            zb[i] = *(const unsigned long long*)(z + off + (size_t)i*TT);
        }
        for (int d0 = 0; d0 < DD; d0 += 8) {
            unsigned long long rn_[8], zn_[8];
            const bool more = (d0 + 8) < DD;
            if (more) {
                #pragma unroll
                for (int i = 0; i < 8; i++) {
                    rn_[i] = *(const unsigned long long*)((const float*)g_resB + off + (size_t)(d0 + 8 + i)*TT);
                    zn_[i] = *(const unsigned long long*)(z + off + (size_t)(d0 + 8 + i)*TT);
                }
            }
            #pragma unroll
            for (int i = 0; i < 8; i++) {
                const int d = d0 + i;
                const float4 wa = *(const float4*)&smf[SM_WO + d*8];
                const float4 wb = *(const float4*)&smf[SM_WO + d*8 + 4];
                unsigned long long dt = ffma2(pk2(wa.x, wa.x), zq2[0], 0ull);
                dt = ffma2(pk2(wa.y, wa.y), zq2[1], dt);
                dt = ffma2(pk2(wa.z, wa.z), zq2[2], dt);
                dt = ffma2(pk2(wa.w, wa.w), zq2[3], dt);
                dt = ffma2(pk2(wb.x, wb.x), zq2[4], dt);
                dt = ffma2(pk2(wb.y, wb.y), zq2[5], dt);
                dt = ffma2(pk2(wb.z, wb.z), zq2[6], dt);
                dt = ffma2(pk2(wb.w, wb.w), zq2[7], dt);
                const float obv = smf[SM_OB + d];
                const unsigned long long pr = fadd2(dt, pk2(obv, obv));
                const unsigned long long r9 = fadd2(rb[i], pr ^ SGN2);   // rn(r8 - pr)
                *(unsigned long long*)&out[off + (size_t)d*TT] = fadd2(zb[i], r9 ^ SGN2); // rn(z - r9)
            }
            if (more) {
                #pragma unroll
                for (int i = 0; i < 8; i++) { rb[i] = rn_[i]; zb[i] = zn_[i]; }
            }
        }
    }

    // ---- loss partial ----
    red[tid] = lacc; __syncthreads();
    for (int s = THREADS/2; s > 0; s >>= 1) {
        if (tid < s) red[tid] += red[tid + s];
        __syncthreads();
    }
    if (tid == 0) g_lpart[blockIdx.x] = red[0];
}

// ---------------------------------------------------------------------------
// Deterministic loss reduce in fp64: cl == cbl (identical forward values)
// ---------------------------------------------------------------------------
__global__ void k_loss(float* __restrict__ out) {
    if (threadIdx.x != 0 || blockIdx.x != 0) return;
    double s = 0.0;
    for (int i = 0; i < NBLK; i++) s += (double)g_lpart[i];
    const float v = (float)(s / 524288.0);   // per-stage mean over B*C*T, summed
    out[OFF_CL]     = v;
    out[OFF_CL + 1] = v;
}

// ---------------------------------------------------------------------------
extern "C" void kernel_launch(void* const* d_in, const int* in_sizes, int n_in,
                              void* d_out, int out_size) {
    (void)in_sizes; (void)n_in; (void)out_size;
    const float* z     = (const float*)d_in[0];
    const float* in_v  = (const float*)d_in[1];
    const float* in_g  = (const float*)d_in[2];
    const float* in_b  = (const float*)d_in[3];
    const float* out_v = (const float*)d_in[4];
    const float* out_g = (const float*)d_in[5];
    const float* out_b = (const float*)d_in[6];
    const float* cb    = (const float*)d_in[7];
    float* out = (float*)d_out;

    cudaFuncSetAttribute(k_mega, cudaFuncAttributeMaxDynamicSharedMemorySize, SMEM_TOT);

    kp_win  <<<72, 256>>>(in_v, in_g);
    kp_wout <<<(NCB*DD + 255)/256, 256>>>(out_v, out_g);
    kp_cb   <<<(NCB*KK + 255)/256, 256>>>(cb);

    k_mega <<<NBLK, THREADS, SMEM_TOT>>>(z, in_b, out_b, cb, out);
    k_loss <<<1, 32>>>(out);
}